// round 3
// baseline (speedup 1.0000x reference)
#include <cuda_runtime.h>
#include <math.h>

// Problem constants
#define S_LEN 2048
#define D_MODEL 2048
#define NB 2
#define NH 16
#define HDIM 128
#define BH (NB*NH)          // 32 batched heads
#define HALF_HD 64

// ---------------------------------------------------------------------------
// Scratch (static device allocations — allowed per harness rules)
// ---------------------------------------------------------------------------
__device__ float g_q  [NB*S_LEN*D_MODEL];                 // 8.4M floats
__device__ float g_k  [NB*S_LEN*D_MODEL];
__device__ float g_v  [NB*S_LEN*D_MODEL];
__device__ float g_att[NB*S_LEN*D_MODEL];
__device__ float g_sc [134217728];                        // 32*2048*2048 scores
__device__ float g_cos[S_LEN*HALF_HD];
__device__ float g_sin[S_LEN*HALF_HD];

// ---------------------------------------------------------------------------
// RoPE tables: cos/sin of s * 10000^(-2i/128)
// ---------------------------------------------------------------------------
__global__ void rope_tables_kernel() {
    int idx = blockIdx.x * blockDim.x + threadIdx.x;
    if (idx >= S_LEN * HALF_HD) return;
    int s = idx / HALF_HD;
    int i = idx % HALF_HD;
    float inv = expf(-((float)(2 * i) / (float)HDIM) * logf(10000.0f));
    float f = (float)s * inv;
    g_cos[idx] = cosf(f);
    g_sin[idx] = sinf(f);
}

// ---------------------------------------------------------------------------
// RoPE apply (in place, on q and k simultaneously)
// ---------------------------------------------------------------------------
__global__ void rope_apply_kernel(float* __restrict__ q, float* __restrict__ k) {
    int idx = blockIdx.x * blockDim.x + threadIdx.x;
    if (idx >= NB * S_LEN * NH * HALF_HD) return;
    int i = idx & 63;
    int h = (idx >> 6) & 15;
    int s = (idx >> 10) & 2047;
    int b = idx >> 21;
    size_t base = ((size_t)(b * S_LEN + s)) * D_MODEL + h * HDIM + i;
    float c  = g_cos[s * HALF_HD + i];
    float sn = g_sin[s * HALF_HD + i];
    float q1 = q[base], q2 = q[base + HALF_HD];
    q[base]           = q1 * c - q2 * sn;
    q[base + HALF_HD] = q1 * sn + q2 * c;
    float k1 = k[base], k2 = k[base + HALF_HD];
    k[base]           = k1 * c - k2 * sn;
    k[base + HALF_HD] = k1 * sn + k2 * c;
}

// ---------------------------------------------------------------------------
// Generic tiled GEMM: C = alpha * A @ B (+ bias), optional B-transpose.
// 128x128 CTA tile, BK=8, 256 threads, 8x8 per-thread microtile.
// Batched via blockIdx.z with (outer,inner) offset decomposition:
//   off = (z/16)*outer + (z%16)*inner
// ---------------------------------------------------------------------------
template<int TRANSB>
__global__ void __launch_bounds__(256)
gemm_kernel(const float* __restrict__ A, int lda,
            const float* __restrict__ Bm, int ldb,
            float* __restrict__ C, int ldc,
            const float* __restrict__ bias,
            int K, float alpha,
            long long aOuter, long long aInner,
            long long bOuter, long long bInner,
            long long cOuter, long long cInner)
{
    __shared__ float As[8][128];
    __shared__ float Bs[8][128];

    int tid = threadIdx.x;
    int tx = tid & 15;          // 0..15 (col group)
    int ty = tid >> 4;          // 0..15 (row group)
    int z = blockIdx.z;
    long long aOff = (long long)(z >> 4) * aOuter + (long long)(z & 15) * aInner;
    long long bOff = (long long)(z >> 4) * bOuter + (long long)(z & 15) * bInner;
    long long cOff = (long long)(z >> 4) * cOuter + (long long)(z & 15) * cInner;

    const float* Ab = A + aOff + (size_t)(blockIdx.y * 128) * lda;
    const float* Bb;
    if (TRANSB) Bb = Bm + bOff + (size_t)(blockIdx.x * 128) * ldb;
    else        Bb = Bm + bOff + (size_t)(blockIdx.x * 128);

    // loader indices
    int lrow = tid >> 1;              // 0..127
    int lk   = (tid & 1) * 4;         // 0 or 4
    int brow = tid >> 5;              // 0..7   (non-trans B)
    int bcol = (tid & 31) * 4;        // 0..124

    float acc[8][8];
    #pragma unroll
    for (int i = 0; i < 8; i++)
        #pragma unroll
        for (int j = 0; j < 8; j++) acc[i][j] = 0.0f;

    for (int k0 = 0; k0 < K; k0 += 8) {
        float4 av = *(const float4*)(Ab + (size_t)lrow * lda + k0 + lk);
        As[lk + 0][lrow] = av.x;
        As[lk + 1][lrow] = av.y;
        As[lk + 2][lrow] = av.z;
        As[lk + 3][lrow] = av.w;
        if (TRANSB) {
            float4 bv = *(const float4*)(Bb + (size_t)lrow * ldb + k0 + lk);
            Bs[lk + 0][lrow] = bv.x;
            Bs[lk + 1][lrow] = bv.y;
            Bs[lk + 2][lrow] = bv.z;
            Bs[lk + 3][lrow] = bv.w;
        } else {
            float4 bv = *(const float4*)(Bb + (size_t)(k0 + brow) * ldb + bcol);
            *(float4*)&Bs[brow][bcol] = bv;
        }
        __syncthreads();

        #pragma unroll
        for (int kk = 0; kk < 8; kk++) {
            float ra[8], rb[8];
            #pragma unroll
            for (int i = 0; i < 8; i++) ra[i] = As[kk][ty * 8 + i];
            #pragma unroll
            for (int j = 0; j < 8; j++) rb[j] = Bs[kk][tx * 8 + j];
            #pragma unroll
            for (int i = 0; i < 8; i++)
                #pragma unroll
                for (int j = 0; j < 8; j++)
                    acc[i][j] = fmaf(ra[i], rb[j], acc[i][j]);
        }
        __syncthreads();
    }

    // epilogue
    int colBase = blockIdx.x * 128 + tx * 8;
    float bvals[8];
    #pragma unroll
    for (int j = 0; j < 8; j++) bvals[j] = bias ? bias[colBase + j] : 0.0f;

    float* Cb = C + cOff + (size_t)(blockIdx.y * 128 + ty * 8) * ldc + colBase;
    #pragma unroll
    for (int i = 0; i < 8; i++) {
        float4 r0, r1;
        r0.x = acc[i][0] * alpha + bvals[0];
        r0.y = acc[i][1] * alpha + bvals[1];
        r0.z = acc[i][2] * alpha + bvals[2];
        r0.w = acc[i][3] * alpha + bvals[3];
        r1.x = acc[i][4] * alpha + bvals[4];
        r1.y = acc[i][5] * alpha + bvals[5];
        r1.z = acc[i][6] * alpha + bvals[6];
        r1.w = acc[i][7] * alpha + bvals[7];
        *(float4*)(Cb + (size_t)i * ldc)     = r0;
        *(float4*)(Cb + (size_t)i * ldc + 4) = r1;
    }
}

// ---------------------------------------------------------------------------
// Row softmax over 2048-wide rows (one CTA per row, 256 threads x 8 elems)
// ---------------------------------------------------------------------------
__global__ void __launch_bounds__(256) softmax_kernel(float* __restrict__ sc) {
    size_t row = blockIdx.x;
    float* p = sc + row * (size_t)S_LEN;
    int tid = threadIdx.x;

    float vals[8];
    float m = -1e30f;
    #pragma unroll
    for (int j = 0; j < 8; j++) {
        vals[j] = p[tid + j * 256];
        m = fmaxf(m, vals[j]);
    }
    __shared__ float red[256];
    red[tid] = m;
    __syncthreads();
    for (int s = 128; s > 0; s >>= 1) {
        if (tid < s) red[tid] = fmaxf(red[tid], red[tid + s]);
        __syncthreads();
    }
    float rowMax = red[0];
    __syncthreads();

    float sum = 0.0f;
    #pragma unroll
    for (int j = 0; j < 8; j++) {
        vals[j] = expf(vals[j] - rowMax);
        sum += vals[j];
    }
    red[tid] = sum;
    __syncthreads();
    for (int s = 128; s > 0; s >>= 1) {
        if (tid < s) red[tid] += red[tid + s];
        __syncthreads();
    }
    float inv = 1.0f / red[0];
    #pragma unroll
    for (int j = 0; j < 8; j++) p[tid + j * 256] = vals[j] * inv;
}

// ---------------------------------------------------------------------------
// Launch
// ---------------------------------------------------------------------------
extern "C" void kernel_launch(void* const* d_in, const int* in_sizes, int n_in,
                              void* d_out, int out_size) {
    const float* x  = (const float*)d_in[0];
    const float* Wq = (const float*)d_in[1];
    const float* bq = (const float*)d_in[2];
    const float* Wk = (const float*)d_in[3];
    const float* bk = (const float*)d_in[4];
    const float* Wv = (const float*)d_in[5];
    const float* bv = (const float*)d_in[6];
    const float* Wo = (const float*)d_in[7];
    const float* bo = (const float*)d_in[8];
    float* out = (float*)d_out;

    float *q, *k, *v, *att, *sc;
    cudaGetSymbolAddress((void**)&q,   g_q);
    cudaGetSymbolAddress((void**)&k,   g_k);
    cudaGetSymbolAddress((void**)&v,   g_v);
    cudaGetSymbolAddress((void**)&att, g_att);
    cudaGetSymbolAddress((void**)&sc,  g_sc);

    // 1. RoPE tables
    rope_tables_kernel<<<(S_LEN * HALF_HD + 255) / 256, 256>>>();

    // 2. QKV projections: [4096,2048] @ [2048,2048] + bias
    dim3 gProj(D_MODEL / 128, (NB * S_LEN) / 128, 1);   // (16, 32)
    gemm_kernel<0><<<gProj, 256>>>(x, D_MODEL, Wq, D_MODEL, q, D_MODEL, bq,
                                   D_MODEL, 1.0f, 0, 0, 0, 0, 0, 0);
    gemm_kernel<0><<<gProj, 256>>>(x, D_MODEL, Wk, D_MODEL, k, D_MODEL, bk,
                                   D_MODEL, 1.0f, 0, 0, 0, 0, 0, 0);
    gemm_kernel<0><<<gProj, 256>>>(x, D_MODEL, Wv, D_MODEL, v, D_MODEL, bv,
                                   D_MODEL, 1.0f, 0, 0, 0, 0, 0, 0);

    // 3. RoPE on q, k (in place)
    rope_apply_kernel<<<(NB * S_LEN * NH * HALF_HD + 255) / 256, 256>>>(q, k);

    // 4. scores = (1/sqrt(128)) * Qr @ Kr^T   per (b,h)
    //    batch z = b*16 + h; offsets: A/B (z/16)*S*D + (z%16)*HD; C z*S*S
    const long long SD = (long long)S_LEN * D_MODEL;
    const long long SS = (long long)S_LEN * S_LEN;
    dim3 gScore(S_LEN / 128, S_LEN / 128, BH);          // (16, 16, 32)
    gemm_kernel<1><<<gScore, 256>>>(q, D_MODEL, k, D_MODEL, sc, S_LEN, nullptr,
                                    HDIM, 0.08838834764831843f,
                                    SD, HDIM, SD, HDIM, 16 * SS, SS);

    // 5. softmax rows
    softmax_kernel<<<BH * S_LEN, 256>>>(sc);

    // 6. att = P @ V  per (b,h): M=2048, N=128, K=2048
    dim3 gPV(1, S_LEN / 128, BH);                       // (1, 16, 32)
    gemm_kernel<0><<<gPV, 256>>>(sc, S_LEN, v, D_MODEL, att, D_MODEL, nullptr,
                                 S_LEN, 1.0f,
                                 16 * SS, SS, SD, HDIM, SD, HDIM);

    // 7. out = att @ Wo + bo
    gemm_kernel<0><<<gProj, 256>>>(att, D_MODEL, Wo, D_MODEL, out, D_MODEL, bo,
                                   D_MODEL, 1.0f, 0, 0, 0, 0, 0, 0);
}

// round 5
// speedup vs baseline: 2.8866x; 2.8866x over previous
#include <cuda_runtime.h>
#include <math.h>
#include <cstdint>

// Problem constants
#define S_LEN 2048
#define D_MODEL 2048
#define NB 2
#define NH 16
#define HDIM 128
#define BH (NB*NH)
#define HALF_HD 64

// ---------------------------------------------------------------------------
// Scratch
// ---------------------------------------------------------------------------
__device__ float g_q  [NB*S_LEN*D_MODEL];
__device__ float g_k  [NB*S_LEN*D_MODEL];
__device__ float g_vt [BH*HDIM*S_LEN];          // V^T per (b,h): [128][2048]
__device__ float g_att[NB*S_LEN*D_MODEL];       // doubles as tf32-rounded x
__device__ float g_sc [134217728];              // 32*2048*2048 scores/probs
__device__ float g_wt [4*D_MODEL*D_MODEL];      // W^T (tf32-rounded)
__device__ float g_cos[S_LEN*HALF_HD];
__device__ float g_sin[S_LEN*HALF_HD];

// ---------------------------------------------------------------------------
// Helpers
// ---------------------------------------------------------------------------
__device__ __forceinline__ float tf32r(float x) {
    uint32_t u = __float_as_uint(x);
    asm("cvt.rna.tf32.f32 %0, %1;" : "=r"(u) : "r"(u));
    return __uint_as_float(u);
}

__device__ __forceinline__ uint32_t smem_u32(const void* p) {
    uint32_t a;
    asm("{ .reg .u64 t; cvta.to.shared.u64 t, %1; cvt.u32.u64 %0, t; }"
        : "=r"(a) : "l"(p));
    return a;
}

__device__ __forceinline__ void cp16(uint32_t dst, const float* src) {
    asm volatile("cp.async.cg.shared.global [%0], [%1], 16;" :: "r"(dst), "l"(src));
}
__device__ __forceinline__ void cp_commit() {
    asm volatile("cp.async.commit_group;");
}
template<int N>
__device__ __forceinline__ void cp_wait() {
    asm volatile("cp.async.wait_group %0;" :: "n"(N));
}

__device__ __forceinline__ void mma_tf32(float* c, const uint32_t* a, const uint32_t* b) {
    asm volatile(
        "mma.sync.aligned.m16n8k8.row.col.f32.tf32.tf32.f32 "
        "{%0,%1,%2,%3}, {%4,%5,%6,%7}, {%8,%9}, {%0,%1,%2,%3};"
        : "+f"(c[0]), "+f"(c[1]), "+f"(c[2]), "+f"(c[3])
        : "r"(a[0]), "r"(a[1]), "r"(a[2]), "r"(a[3]), "r"(b[0]), "r"(b[1]));
}

// ---------------------------------------------------------------------------
// RoPE tables
// ---------------------------------------------------------------------------
__global__ void rope_tables_kernel() {
    int idx = blockIdx.x * blockDim.x + threadIdx.x;
    if (idx >= S_LEN * HALF_HD) return;
    int s = idx / HALF_HD;
    int i = idx % HALF_HD;
    float inv = expf(-((float)(2 * i) / (float)HDIM) * logf(10000.0f));
    float f = (float)s * inv;
    g_cos[idx] = cosf(f);
    g_sin[idx] = sinf(f);
}

// ---------------------------------------------------------------------------
// x -> tf32-rounded copy
// ---------------------------------------------------------------------------
__global__ void round_copy_kernel(const float* __restrict__ in, float* __restrict__ out, int n) {
    int i = blockIdx.x * blockDim.x + threadIdx.x;
    if (i < n) out[i] = tf32r(in[i]);
}

// ---------------------------------------------------------------------------
// 2048x2048 transpose with tf32 rounding (for W^T)
// ---------------------------------------------------------------------------
__global__ void transpose_kernel(const float* __restrict__ in, float* __restrict__ out) {
    __shared__ float t[32][33];
    int x = blockIdx.x * 32 + threadIdx.x;
    int y = blockIdx.y * 32 + threadIdx.y;
    #pragma unroll
    for (int j = 0; j < 32; j += 8)
        t[threadIdx.y + j][threadIdx.x] = tf32r(in[(size_t)(y + j) * D_MODEL + x]);
    __syncthreads();
    x = blockIdx.y * 32 + threadIdx.x;
    y = blockIdx.x * 32 + threadIdx.y;
    #pragma unroll
    for (int j = 0; j < 32; j += 8)
        out[(size_t)(y + j) * D_MODEL + x] = t[threadIdx.x][threadIdx.y + j];
}

// ---------------------------------------------------------------------------
// tf32 mma.sync GEMM. 128x128 CTA tile, BK=32, 256 threads (8 warps, 2x4),
// warp tile 64x32, cp.async double-buffered.
// A: [M,K] row-major (lda). B: [N,K] K-major (ldb). C = alpha*A@B^T (+bias).
// EPI: 0 plain, 1 RoPE fused, 2 write V^T. ROUND: tf32-round outputs.
// Batched via blockIdx.z: off = (z>>4)*outer + (z&15)*inner.
// ---------------------------------------------------------------------------
#define SROW 36                         // padded smem row (floats)
#define TILE_F (128*SROW)               // 4608 floats per matrix tile
#define GEMM_SMEM_SZ (2*2*TILE_F*4)     // 73728 bytes
#define CSTR 132                        // C staging row stride (floats)

template<int EPI, int ROUND>
__global__ void __launch_bounds__(256)
tc_gemm(const float* __restrict__ A, int lda,
        const float* __restrict__ Bm, int ldb,
        float* __restrict__ C, int ldc,
        const float* __restrict__ bias,
        int K, float alpha,
        long long aOuter, long long aInner,
        long long bOuter, long long bInner,
        long long cOuter, long long cInner)
{
    extern __shared__ char smem_raw[];
    float* sbase = (float*)smem_raw;
    const uint32_t s_u32 = smem_u32(smem_raw);

    const int tid  = threadIdx.x;
    const int wid  = tid >> 5;
    const int lane = tid & 31;
    const int group = lane >> 2;
    const int qd    = lane & 3;
    const int wm = (wid >> 2) * 64;     // 0 or 64
    const int wn = (wid & 3) * 32;      // 0,32,64,96

    const int z = blockIdx.z;
    const long long aOff = (long long)(z >> 4) * aOuter + (long long)(z & 15) * aInner;
    const long long bOff = (long long)(z >> 4) * bOuter + (long long)(z & 15) * bInner;
    const long long cOff = (long long)(z >> 4) * cOuter + (long long)(z & 15) * cInner;

    const int m0 = blockIdx.y * 128;
    const int n0 = blockIdx.x * 128;
    const float* Ag = A + aOff + (size_t)m0 * lda;
    const float* Bg = Bm + bOff + (size_t)n0 * ldb;

    // loader geometry: 1024 float4 per tile, 4 per thread
    const int lrow[4] = { (tid + 0) >> 3, (tid + 256) >> 3, (tid + 512) >> 3, (tid + 768) >> 3 };
    const int lc4 = (tid & 7) * 4;

    float acc[4][4][4];
    #pragma unroll
    for (int mt = 0; mt < 4; mt++)
        #pragma unroll
        for (int nt = 0; nt < 4; nt++)
            #pragma unroll
            for (int i = 0; i < 4; i++) acc[mt][nt][i] = 0.0f;

    const int nch = K >> 5;

    // prologue: stage 0
    {
        uint32_t sa = s_u32;
        uint32_t sb = s_u32 + TILE_F * 4;
        #pragma unroll
        for (int i = 0; i < 4; i++) {
            int r = lrow[i];
            uint32_t so = (uint32_t)(r * SROW + lc4) * 4;
            cp16(sa + so, Ag + (size_t)r * lda + lc4);
            cp16(sb + so, Bg + (size_t)r * ldb + lc4);
        }
        cp_commit();
    }

    for (int ch = 0; ch < nch; ch++) {
        const int st = ch & 1;
        if (ch + 1 < nch) {
            const int k0 = (ch + 1) << 5;
            uint32_t sa = s_u32 + (uint32_t)((ch + 1) & 1) * (2 * TILE_F * 4);
            uint32_t sb = sa + TILE_F * 4;
            #pragma unroll
            for (int i = 0; i < 4; i++) {
                int r = lrow[i];
                uint32_t so = (uint32_t)(r * SROW + lc4) * 4;
                cp16(sa + so, Ag + (size_t)r * lda + k0 + lc4);
                cp16(sb + so, Bg + (size_t)r * ldb + k0 + lc4);
            }
            cp_commit();
            cp_wait<1>();
        } else {
            cp_wait<0>();
        }
        __syncthreads();

        const float* As = sbase + st * 2 * TILE_F;
        const float* Bs = As + TILE_F;

        #pragma unroll
        for (int kk = 0; kk < 4; kk++) {
            const int colk = kk * 8 + qd;
            uint32_t af[4][4], bf[4][2];
            #pragma unroll
            for (int mt = 0; mt < 4; mt++) {
                int r0 = wm + mt * 16 + group;
                af[mt][0] = __float_as_uint(As[r0 * SROW + colk]);
                af[mt][1] = __float_as_uint(As[(r0 + 8) * SROW + colk]);
                af[mt][2] = __float_as_uint(As[r0 * SROW + colk + 4]);
                af[mt][3] = __float_as_uint(As[(r0 + 8) * SROW + colk + 4]);
            }
            #pragma unroll
            for (int nt = 0; nt < 4; nt++) {
                int bn = wn + nt * 8 + group;
                bf[nt][0] = __float_as_uint(Bs[bn * SROW + colk]);
                bf[nt][1] = __float_as_uint(Bs[bn * SROW + colk + 4]);
            }
            #pragma unroll
            for (int mt = 0; mt < 4; mt++)
                #pragma unroll
                for (int nt = 0; nt < 4; nt++)
                    mma_tf32(acc[mt][nt], af[mt], bf[nt]);
        }
        __syncthreads();
    }

    // ---- stage C tile into smem (reuses the A/B buffers) ----
    float* Cs = sbase;
    #pragma unroll
    for (int mt = 0; mt < 4; mt++) {
        int r0 = wm + mt * 16 + group;
        #pragma unroll
        for (int nt = 0; nt < 4; nt++) {
            int cb = wn + nt * 8 + 2 * qd;
            Cs[r0 * CSTR + cb]           = acc[mt][nt][0] * alpha;
            Cs[r0 * CSTR + cb + 1]       = acc[mt][nt][1] * alpha;
            Cs[(r0 + 8) * CSTR + cb]     = acc[mt][nt][2] * alpha;
            Cs[(r0 + 8) * CSTR + cb + 1] = acc[mt][nt][3] * alpha;
        }
    }
    __syncthreads();

    // ---- writers ----
    if (EPI == 0) {
        const int col4 = (tid & 31) * 4;
        float bv[4] = {0, 0, 0, 0};
        if (bias) {
            bv[0] = __ldg(bias + n0 + col4);
            bv[1] = __ldg(bias + n0 + col4 + 1);
            bv[2] = __ldg(bias + n0 + col4 + 2);
            bv[3] = __ldg(bias + n0 + col4 + 3);
        }
        #pragma unroll
        for (int i = 0; i < 16; i++) {
            int row = (tid >> 5) + i * 8;
            const float* src = Cs + row * CSTR + col4;
            float4 v;
            v.x = src[0] + bv[0];
            v.y = src[1] + bv[1];
            v.z = src[2] + bv[2];
            v.w = src[3] + bv[3];
            if (ROUND) {
                v.x = tf32r(v.x); v.y = tf32r(v.y);
                v.z = tf32r(v.z); v.w = tf32r(v.w);
            }
            *(float4*)(C + cOff + (size_t)(m0 + row) * ldc + n0 + col4) = v;
        }
    } else if (EPI == 1) {
        // fused RoPE: pair (ci, ci+64) within the 128-wide head tile
        #pragma unroll
        for (int i = 0; i < 32; i++) {
            int flat = i * 256 + tid;
            int row = flat >> 6;
            int ci = flat & 63;
            float v1 = Cs[row * CSTR + ci]      + __ldg(bias + n0 + ci);
            float v2 = Cs[row * CSTR + ci + 64] + __ldg(bias + n0 + ci + 64);
            int s = (m0 + row) & (S_LEN - 1);
            float cv = g_cos[s * HALF_HD + ci];
            float sv = g_sin[s * HALF_HD + ci];
            float o1 = v1 * cv - v2 * sv;
            float o2 = v1 * sv + v2 * cv;
            float* dst = C + (size_t)(m0 + row) * ldc + n0 + ci;
            dst[0]  = tf32r(o1);
            dst[64] = tf32r(o2);
        }
    } else {
        // EPI == 2: write V^T: vt[((b*16+h)*128 + d)*S_LEN + s]
        const int h = n0 >> 7;
        #pragma unroll
        for (int i = 0; i < 64; i++) {
            int flat = i * 256 + tid;
            int sl = flat & 127;
            int d = flat >> 7;
            float v = Cs[sl * CSTR + d] + __ldg(bias + n0 + d);
            int b = (m0 + sl) >> 11;
            int s = (m0 + sl) & (S_LEN - 1);
            C[((size_t)(b * NH + h) * HDIM + d) * S_LEN + s] = tf32r(v);
        }
    }
}

// ---------------------------------------------------------------------------
// Row softmax over 2048-wide rows (writes tf32-rounded probabilities)
// ---------------------------------------------------------------------------
__global__ void __launch_bounds__(256) softmax_kernel(float* __restrict__ sc) {
    size_t row = blockIdx.x;
    float* p = sc + row * (size_t)S_LEN;
    int tid = threadIdx.x;

    float vals[8];
    float m = -1e30f;
    #pragma unroll
    for (int j = 0; j < 8; j++) {
        vals[j] = p[tid + j * 256];
        m = fmaxf(m, vals[j]);
    }
    __shared__ float red[256];
    red[tid] = m;
    __syncthreads();
    for (int s = 128; s > 0; s >>= 1) {
        if (tid < s) red[tid] = fmaxf(red[tid], red[tid + s]);
        __syncthreads();
    }
    float rowMax = red[0];
    __syncthreads();

    float sum = 0.0f;
    #pragma unroll
    for (int j = 0; j < 8; j++) {
        vals[j] = __expf(vals[j] - rowMax);
        sum += vals[j];
    }
    red[tid] = sum;
    __syncthreads();
    for (int s = 128; s > 0; s >>= 1) {
        if (tid < s) red[tid] += red[tid + s];
        __syncthreads();
    }
    float inv = 1.0f / red[0];
    #pragma unroll
    for (int j = 0; j < 8; j++) p[tid + j * 256] = tf32r(vals[j] * inv);
}

// ---------------------------------------------------------------------------
// Launch
// ---------------------------------------------------------------------------
extern "C" void kernel_launch(void* const* d_in, const int* in_sizes, int n_in,
                              void* d_out, int out_size) {
    const float* x  = (const float*)d_in[0];
    const float* Wq = (const float*)d_in[1];
    const float* bq = (const float*)d_in[2];
    const float* Wk = (const float*)d_in[3];
    const float* bk = (const float*)d_in[4];
    const float* Wv = (const float*)d_in[5];
    const float* bv = (const float*)d_in[6];
    const float* Wo = (const float*)d_in[7];
    const float* bo = (const float*)d_in[8];
    float* out = (float*)d_out;

    float *q, *k, *vt, *att, *sc, *wt;
    cudaGetSymbolAddress((void**)&q,   g_q);
    cudaGetSymbolAddress((void**)&k,   g_k);
    cudaGetSymbolAddress((void**)&vt,  g_vt);
    cudaGetSymbolAddress((void**)&att, g_att);
    cudaGetSymbolAddress((void**)&sc,  g_sc);
    cudaGetSymbolAddress((void**)&wt,  g_wt);
    float* wt0 = wt;
    float* wt1 = wt + (size_t)D_MODEL * D_MODEL;
    float* wt2 = wt + 2 * (size_t)D_MODEL * D_MODEL;
    float* wt3 = wt + 3 * (size_t)D_MODEL * D_MODEL;
    float* xr = att;   // reuse att scratch for tf32-rounded x (free before PV)

    cudaFuncSetAttribute((const void*)tc_gemm<0,0>,
                         cudaFuncAttributeMaxDynamicSharedMemorySize, GEMM_SMEM_SZ);
    cudaFuncSetAttribute((const void*)tc_gemm<0,1>,
                         cudaFuncAttributeMaxDynamicSharedMemorySize, GEMM_SMEM_SZ);
    cudaFuncSetAttribute((const void*)tc_gemm<1,1>,
                         cudaFuncAttributeMaxDynamicSharedMemorySize, GEMM_SMEM_SZ);
    cudaFuncSetAttribute((const void*)tc_gemm<2,1>,
                         cudaFuncAttributeMaxDynamicSharedMemorySize, GEMM_SMEM_SZ);

    // 0. Pre-processing: W^T (rounded), x rounded, RoPE tables
    dim3 tb(32, 8);
    dim3 tg(D_MODEL / 32, D_MODEL / 32);
    transpose_kernel<<<tg, tb>>>(Wq, wt0);
    transpose_kernel<<<tg, tb>>>(Wk, wt1);
    transpose_kernel<<<tg, tb>>>(Wv, wt2);
    transpose_kernel<<<tg, tb>>>(Wo, wt3);
    int nx = NB * S_LEN * D_MODEL;
    round_copy_kernel<<<(nx + 255) / 256, 256>>>(x, xr, nx);
    rope_tables_kernel<<<(S_LEN * HALF_HD + 255) / 256, 256>>>();

    // 1. Q/K projections (fused RoPE); V projection (fused transpose)
    dim3 gProj(D_MODEL / 128, (NB * S_LEN) / 128, 1);   // (16, 32)
    tc_gemm<1,1><<<gProj, 256, GEMM_SMEM_SZ>>>(xr, D_MODEL, wt0, D_MODEL, q, D_MODEL,
                                               bq, D_MODEL, 1.0f, 0,0, 0,0, 0,0);
    tc_gemm<1,1><<<gProj, 256, GEMM_SMEM_SZ>>>(xr, D_MODEL, wt1, D_MODEL, k, D_MODEL,
                                               bk, D_MODEL, 1.0f, 0,0, 0,0, 0,0);
    tc_gemm<2,1><<<gProj, 256, GEMM_SMEM_SZ>>>(xr, D_MODEL, wt2, D_MODEL, vt, D_MODEL,
                                               bv, D_MODEL, 1.0f, 0,0, 0,0, 0,0);

    // 2. scores = (1/sqrt(128)) * Qr @ Kr^T per (b,h)
    const long long SD = (long long)S_LEN * D_MODEL;
    const long long SS = (long long)S_LEN * S_LEN;
    dim3 gScore(S_LEN / 128, S_LEN / 128, BH);          // (16, 16, 32)
    tc_gemm<0,0><<<gScore, 256, GEMM_SMEM_SZ>>>(q, D_MODEL, k, D_MODEL, sc, S_LEN,
                                                nullptr, HDIM, 0.08838834764831843f,
                                                SD, HDIM, SD, HDIM, 16 * SS, SS);

    // 3. softmax rows (rounds probs to tf32)
    softmax_kernel<<<BH * S_LEN, 256>>>(sc);

    // 4. att = P @ V (B = V^T, K-major); overwrites xr — safe, xr no longer needed
    const long long VTB = (long long)NH * HDIM * S_LEN;
    const long long VTH = (long long)HDIM * S_LEN;
    dim3 gPV(1, S_LEN / 128, BH);                       // (1, 16, 32)
    tc_gemm<0,1><<<gPV, 256, GEMM_SMEM_SZ>>>(sc, S_LEN, vt, S_LEN, att, D_MODEL,
                                             nullptr, S_LEN, 1.0f,
                                             16 * SS, SS, VTB, VTH, SD, HDIM);

    // 5. out = att @ Wo + bo
    tc_gemm<0,0><<<gProj, 256, GEMM_SMEM_SZ>>>(att, D_MODEL, wt3, D_MODEL, out, D_MODEL,
                                               bo, D_MODEL, 1.0f, 0,0, 0,0, 0,0);
}

// round 6
// speedup vs baseline: 3.4084x; 1.1808x over previous
#include <cuda_runtime.h>
#include <math.h>
#include <cstdint>

// Problem constants
#define S_LEN 2048
#define D_MODEL 2048
#define NB 2
#define NH 16
#define HDIM 128
#define BH (NB*NH)
#define HALF_HD 64

// ---------------------------------------------------------------------------
// Scratch
// ---------------------------------------------------------------------------
__device__ float g_q  [NB*S_LEN*D_MODEL];
__device__ float g_k  [NB*S_LEN*D_MODEL];
__device__ float g_vt [BH*HDIM*S_LEN];          // V^T per (b,h): [128][2048]
__device__ float g_att[NB*S_LEN*D_MODEL];       // doubles as tf32-rounded x
__device__ float g_wt [4*D_MODEL*D_MODEL];      // W^T (tf32-rounded)
__device__ float g_cos[S_LEN*HALF_HD];
__device__ float g_sin[S_LEN*HALF_HD];

// ---------------------------------------------------------------------------
// Helpers
// ---------------------------------------------------------------------------
__device__ __forceinline__ float tf32r(float x) {
    uint32_t u = __float_as_uint(x);
    asm("cvt.rna.tf32.f32 %0, %1;" : "=r"(u) : "r"(u));
    return __uint_as_float(u);
}

__device__ __forceinline__ uint32_t smem_u32(const void* p) {
    uint32_t a;
    asm("{ .reg .u64 t; cvta.to.shared.u64 t, %1; cvt.u32.u64 %0, t; }"
        : "=r"(a) : "l"(p));
    return a;
}

__device__ __forceinline__ void cp16(uint32_t dst, const float* src) {
    asm volatile("cp.async.cg.shared.global [%0], [%1], 16;" :: "r"(dst), "l"(src));
}
__device__ __forceinline__ void cp_commit() {
    asm volatile("cp.async.commit_group;");
}
template<int N>
__device__ __forceinline__ void cp_wait() {
    asm volatile("cp.async.wait_group %0;" :: "n"(N));
}

__device__ __forceinline__ void mma_tf32(float* c, const uint32_t* a, const uint32_t* b) {
    asm volatile(
        "mma.sync.aligned.m16n8k8.row.col.f32.tf32.tf32.f32 "
        "{%0,%1,%2,%3}, {%4,%5,%6,%7}, {%8,%9}, {%0,%1,%2,%3};"
        : "+f"(c[0]), "+f"(c[1]), "+f"(c[2]), "+f"(c[3])
        : "r"(a[0]), "r"(a[1]), "r"(a[2]), "r"(a[3]), "r"(b[0]), "r"(b[1]));
}

// ---------------------------------------------------------------------------
// RoPE tables
// ---------------------------------------------------------------------------
__global__ void rope_tables_kernel() {
    int idx = blockIdx.x * blockDim.x + threadIdx.x;
    if (idx >= S_LEN * HALF_HD) return;
    int s = idx / HALF_HD;
    int i = idx % HALF_HD;
    float inv = expf(-((float)(2 * i) / (float)HDIM) * logf(10000.0f));
    float f = (float)s * inv;
    g_cos[idx] = cosf(f);
    g_sin[idx] = sinf(f);
}

// ---------------------------------------------------------------------------
// x -> tf32-rounded copy
// ---------------------------------------------------------------------------
__global__ void round_copy_kernel(const float* __restrict__ in, float* __restrict__ out, int n) {
    int i = blockIdx.x * blockDim.x + threadIdx.x;
    if (i < n) out[i] = tf32r(in[i]);
}

// ---------------------------------------------------------------------------
// 2048x2048 transpose with tf32 rounding (for W^T)
// ---------------------------------------------------------------------------
__global__ void transpose_kernel(const float* __restrict__ in, float* __restrict__ out) {
    __shared__ float t[32][33];
    int x = blockIdx.x * 32 + threadIdx.x;
    int y = blockIdx.y * 32 + threadIdx.y;
    #pragma unroll
    for (int j = 0; j < 32; j += 8)
        t[threadIdx.y + j][threadIdx.x] = tf32r(in[(size_t)(y + j) * D_MODEL + x]);
    __syncthreads();
    x = blockIdx.y * 32 + threadIdx.x;
    y = blockIdx.x * 32 + threadIdx.y;
    #pragma unroll
    for (int j = 0; j < 32; j += 8)
        out[(size_t)(y + j) * D_MODEL + x] = t[threadIdx.x][threadIdx.y + j];
}

// ---------------------------------------------------------------------------
// tf32 mma.sync GEMM (projections). 128x128 CTA tile, BK=32, 256 threads,
// warp tile 64x32, cp.async double-buffered.
// A: [M,K] row-major. B: [N,K] K-major. C = alpha*A@B^T (+bias).
// EPI: 0 plain, 1 RoPE fused, 2 write V^T. ROUND: tf32-round outputs.
// ---------------------------------------------------------------------------
#define SROW 36
#define TILE_F (128*SROW)
#define GEMM_SMEM_SZ (2*2*TILE_F*4)
#define CSTR 132

template<int EPI, int ROUND>
__global__ void __launch_bounds__(256)
tc_gemm(const float* __restrict__ A, int lda,
        const float* __restrict__ Bm, int ldb,
        float* __restrict__ C, int ldc,
        const float* __restrict__ bias,
        int K, float alpha)
{
    extern __shared__ char smem_raw[];
    float* sbase = (float*)smem_raw;
    const uint32_t s_u32 = smem_u32(smem_raw);

    const int tid  = threadIdx.x;
    const int wid  = tid >> 5;
    const int lane = tid & 31;
    const int group = lane >> 2;
    const int qd    = lane & 3;
    const int wm = (wid >> 2) * 64;
    const int wn = (wid & 3) * 32;

    const int m0 = blockIdx.y * 128;
    const int n0 = blockIdx.x * 128;
    const float* Ag = A + (size_t)m0 * lda;
    const float* Bg = Bm + (size_t)n0 * ldb;

    const int lrow[4] = { (tid + 0) >> 3, (tid + 256) >> 3, (tid + 512) >> 3, (tid + 768) >> 3 };
    const int lc4 = (tid & 7) * 4;

    float acc[4][4][4];
    #pragma unroll
    for (int mt = 0; mt < 4; mt++)
        #pragma unroll
        for (int nt = 0; nt < 4; nt++)
            #pragma unroll
            for (int i = 0; i < 4; i++) acc[mt][nt][i] = 0.0f;

    const int nch = K >> 5;

    {
        uint32_t sa = s_u32;
        uint32_t sb = s_u32 + TILE_F * 4;
        #pragma unroll
        for (int i = 0; i < 4; i++) {
            int r = lrow[i];
            uint32_t so = (uint32_t)(r * SROW + lc4) * 4;
            cp16(sa + so, Ag + (size_t)r * lda + lc4);
            cp16(sb + so, Bg + (size_t)r * ldb + lc4);
        }
        cp_commit();
    }

    for (int ch = 0; ch < nch; ch++) {
        const int st = ch & 1;
        if (ch + 1 < nch) {
            const int k0 = (ch + 1) << 5;
            uint32_t sa = s_u32 + (uint32_t)((ch + 1) & 1) * (2 * TILE_F * 4);
            uint32_t sb = sa + TILE_F * 4;
            #pragma unroll
            for (int i = 0; i < 4; i++) {
                int r = lrow[i];
                uint32_t so = (uint32_t)(r * SROW + lc4) * 4;
                cp16(sa + so, Ag + (size_t)r * lda + k0 + lc4);
                cp16(sb + so, Bg + (size_t)r * ldb + k0 + lc4);
            }
            cp_commit();
            cp_wait<1>();
        } else {
            cp_wait<0>();
        }
        __syncthreads();

        const float* As = sbase + st * 2 * TILE_F;
        const float* Bs = As + TILE_F;

        #pragma unroll
        for (int kk = 0; kk < 4; kk++) {
            const int colk = kk * 8 + qd;
            uint32_t af[4][4], bf[4][2];
            #pragma unroll
            for (int mt = 0; mt < 4; mt++) {
                int r0 = wm + mt * 16 + group;
                af[mt][0] = __float_as_uint(As[r0 * SROW + colk]);
                af[mt][1] = __float_as_uint(As[(r0 + 8) * SROW + colk]);
                af[mt][2] = __float_as_uint(As[r0 * SROW + colk + 4]);
                af[mt][3] = __float_as_uint(As[(r0 + 8) * SROW + colk + 4]);
            }
            #pragma unroll
            for (int nt = 0; nt < 4; nt++) {
                int bn = wn + nt * 8 + group;
                bf[nt][0] = __float_as_uint(Bs[bn * SROW + colk]);
                bf[nt][1] = __float_as_uint(Bs[bn * SROW + colk + 4]);
            }
            #pragma unroll
            for (int mt = 0; mt < 4; mt++)
                #pragma unroll
                for (int nt = 0; nt < 4; nt++)
                    mma_tf32(acc[mt][nt], af[mt], bf[nt]);
        }
        __syncthreads();
    }

    // stage C in smem
    float* Cs = sbase;
    #pragma unroll
    for (int mt = 0; mt < 4; mt++) {
        int r0 = wm + mt * 16 + group;
        #pragma unroll
        for (int nt = 0; nt < 4; nt++) {
            int cb = wn + nt * 8 + 2 * qd;
            Cs[r0 * CSTR + cb]           = acc[mt][nt][0] * alpha;
            Cs[r0 * CSTR + cb + 1]       = acc[mt][nt][1] * alpha;
            Cs[(r0 + 8) * CSTR + cb]     = acc[mt][nt][2] * alpha;
            Cs[(r0 + 8) * CSTR + cb + 1] = acc[mt][nt][3] * alpha;
        }
    }
    __syncthreads();

    if (EPI == 0) {
        const int col4 = (tid & 31) * 4;
        float bv[4] = {0, 0, 0, 0};
        if (bias) {
            bv[0] = __ldg(bias + n0 + col4);
            bv[1] = __ldg(bias + n0 + col4 + 1);
            bv[2] = __ldg(bias + n0 + col4 + 2);
            bv[3] = __ldg(bias + n0 + col4 + 3);
        }
        #pragma unroll
        for (int i = 0; i < 16; i++) {
            int row = (tid >> 5) + i * 8;
            const float* src = Cs + row * CSTR + col4;
            float4 v;
            v.x = src[0] + bv[0];
            v.y = src[1] + bv[1];
            v.z = src[2] + bv[2];
            v.w = src[3] + bv[3];
            if (ROUND) {
                v.x = tf32r(v.x); v.y = tf32r(v.y);
                v.z = tf32r(v.z); v.w = tf32r(v.w);
            }
            *(float4*)(C + (size_t)(m0 + row) * ldc + n0 + col4) = v;
        }
    } else if (EPI == 1) {
        #pragma unroll
        for (int i = 0; i < 32; i++) {
            int flat = i * 256 + tid;
            int row = flat >> 6;
            int ci = flat & 63;
            float v1 = Cs[row * CSTR + ci]      + __ldg(bias + n0 + ci);
            float v2 = Cs[row * CSTR + ci + 64] + __ldg(bias + n0 + ci + 64);
            int s = (m0 + row) & (S_LEN - 1);
            float cv = g_cos[s * HALF_HD + ci];
            float sv = g_sin[s * HALF_HD + ci];
            float o1 = v1 * cv - v2 * sv;
            float o2 = v1 * sv + v2 * cv;
            float* dst = C + (size_t)(m0 + row) * ldc + n0 + ci;
            dst[0]  = tf32r(o1);
            dst[64] = tf32r(o2);
        }
    } else {
        const int h = n0 >> 7;
        #pragma unroll
        for (int i = 0; i < 64; i++) {
            int flat = i * 256 + tid;
            int sl = flat & 127;
            int d = flat >> 7;
            float v = Cs[sl * CSTR + d] + __ldg(bias + n0 + d);
            int b = (m0 + sl) >> 11;
            int s = (m0 + sl) & (S_LEN - 1);
            C[((size_t)(b * NH + h) * HDIM + d) * S_LEN + s] = tf32r(v);
        }
    }
}

// ---------------------------------------------------------------------------
// Flash attention: per (q-tile 128, bh). 256 threads, 8 warps x (16 rows, 128 cols).
// Online softmax; K/V tiles pipelined across phases (V loads during QK^T,
// K(i+1) loads during softmax+PV). Q held as A-fragments in registers.
// Inputs q,k (rows [b,s], head cols h*128, tf32), vt ([bh][d][s], tf32).
// Output att [b,s,2048], tf32-rounded.
// ---------------------------------------------------------------------------
#define FA_SROW 132
#define FA_TILE (128*FA_SROW)
#define FA_SMEM_SZ (3*FA_TILE*4)      // 202752 bytes

__global__ void __launch_bounds__(256, 1)
fa_kernel(const float* __restrict__ q, const float* __restrict__ k,
          const float* __restrict__ vt, float* __restrict__ att)
{
    extern __shared__ float sm[];
    float* sQP = sm;
    float* sK  = sm + FA_TILE;
    float* sV  = sm + 2 * FA_TILE;
    const uint32_t uQP = smem_u32(sQP);
    const uint32_t uK  = smem_u32(sK);
    const uint32_t uV  = smem_u32(sV);

    const int tid = threadIdx.x;
    const int wid = tid >> 5;
    const int lane = tid & 31;
    const int group = lane >> 2;
    const int qd = lane & 3;
    const int bh = blockIdx.y;
    const int b = bh >> 4, h = bh & 15;
    const int q0 = blockIdx.x * 128;

    const float* Qg = q + ((size_t)(b * S_LEN + q0)) * D_MODEL + h * HDIM;
    const float* Kg = k + ((size_t)b * S_LEN) * D_MODEL + h * HDIM;
    const float* Vg = vt + (size_t)bh * HDIM * S_LEN;

    const int lr = tid >> 3;             // will cover rows via +32 steps
    const int lc = (tid & 7) * 4;        // 0..28 (x4 floats)
    // Q tile load (128 rows x 128 cols): 4 rows-per-thread pattern x (32 float4/row)
    #pragma unroll
    for (int i = 0; i < 16; i++) {
        int idx = i * 256 + tid;
        int r = idx >> 5, c = (idx & 31) * 4;
        cp16(uQP + (uint32_t)(r * FA_SROW + c) * 4, Qg + (size_t)r * D_MODEL + c);
    }
    cp_commit();
    // K(0)
    #pragma unroll
    for (int i = 0; i < 16; i++) {
        int idx = i * 256 + tid;
        int r = idx >> 5, c = (idx & 31) * 4;
        cp16(uK + (uint32_t)(r * FA_SROW + c) * 4, Kg + (size_t)r * D_MODEL + c);
    }
    cp_commit();
    cp_wait<1>();
    __syncthreads();

    // Q A-fragments for all 16 k-steps (row-pair group/group+8 of warp's 16 rows)
    uint32_t qa[16][4];
    {
        const float* base = sQP + (wid * 16 + group) * FA_SROW;
        #pragma unroll
        for (int kk = 0; kk < 16; kk++) {
            qa[kk][0] = __float_as_uint(base[kk * 8 + qd]);
            qa[kk][1] = __float_as_uint(base[8 * FA_SROW + kk * 8 + qd]);
            qa[kk][2] = __float_as_uint(base[kk * 8 + qd + 4]);
            qa[kk][3] = __float_as_uint(base[8 * FA_SROW + kk * 8 + qd + 4]);
        }
    }
    __syncthreads();
    // V(0)
    #pragma unroll
    for (int i = 0; i < 16; i++) {
        int idx = i * 256 + tid;
        int r = idx >> 5, c = (idx & 31) * 4;
        cp16(uV + (uint32_t)(r * FA_SROW + c) * 4, Vg + (size_t)r * S_LEN + c);
    }
    cp_commit();

    const float alpha = 0.08838834764831843f;
    float m0 = -1e30f, m1 = -1e30f, l0 = 0.0f, l1 = 0.0f;
    float oacc[16][4];
    #pragma unroll
    for (int nt = 0; nt < 16; nt++)
        #pragma unroll
        for (int i = 0; i < 4; i++) oacc[nt][i] = 0.0f;

    float* prow = sQP + (wid * 16 + group) * FA_SROW;

    for (int it = 0; it < 16; it++) {
        cp_wait<1>();            // K(it) complete (V(it) may be in flight)
        __syncthreads();

        // ---- S = Q @ K^T ----
        float sacc[16][4];
        #pragma unroll
        for (int nt = 0; nt < 16; nt++)
            #pragma unroll
            for (int i = 0; i < 4; i++) sacc[nt][i] = 0.0f;

        #pragma unroll
        for (int kk = 0; kk < 16; kk++) {
            const int colk = kk * 8 + qd;
            #pragma unroll
            for (int nt = 0; nt < 16; nt++) {
                uint32_t bf[2];
                const float* bp = sK + (nt * 8 + group) * FA_SROW + colk;
                bf[0] = __float_as_uint(bp[0]);
                bf[1] = __float_as_uint(bp[4]);
                mma_tf32(sacc[nt], qa[kk], bf);
            }
        }
        __syncthreads();         // everyone done reading sK
        if (it + 1 < 16) {       // K(it+1) load overlaps softmax+PV
            const float* Kn = Kg + (size_t)(it + 1) * 128 * D_MODEL;
            #pragma unroll
            for (int i = 0; i < 16; i++) {
                int idx = i * 256 + tid;
                int r = idx >> 5, c = (idx & 31) * 4;
                cp16(uK + (uint32_t)(r * FA_SROW + c) * 4, Kn + (size_t)r * D_MODEL + c);
            }
            cp_commit();
        }

        // ---- online softmax (rows group / group+8, lane-quad reductions) ----
        float mxa = -1e30f, mxb = -1e30f;
        #pragma unroll
        for (int nt = 0; nt < 16; nt++) {
            sacc[nt][0] *= alpha; sacc[nt][1] *= alpha;
            sacc[nt][2] *= alpha; sacc[nt][3] *= alpha;
            mxa = fmaxf(mxa, fmaxf(sacc[nt][0], sacc[nt][1]));
            mxb = fmaxf(mxb, fmaxf(sacc[nt][2], sacc[nt][3]));
        }
        mxa = fmaxf(mxa, __shfl_xor_sync(0xFFFFFFFF, mxa, 1));
        mxa = fmaxf(mxa, __shfl_xor_sync(0xFFFFFFFF, mxa, 2));
        mxb = fmaxf(mxb, __shfl_xor_sync(0xFFFFFFFF, mxb, 1));
        mxb = fmaxf(mxb, __shfl_xor_sync(0xFFFFFFFF, mxb, 2));
        float na = fmaxf(m0, mxa), nb = fmaxf(m1, mxb);
        float fa_ = __expf(m0 - na), fb_ = __expf(m1 - nb);
        float psa = 0.0f, psb = 0.0f;
        #pragma unroll
        for (int nt = 0; nt < 16; nt++) {
            sacc[nt][0] = __expf(sacc[nt][0] - na);
            sacc[nt][1] = __expf(sacc[nt][1] - na);
            sacc[nt][2] = __expf(sacc[nt][2] - nb);
            sacc[nt][3] = __expf(sacc[nt][3] - nb);
            psa += sacc[nt][0] + sacc[nt][1];
            psb += sacc[nt][2] + sacc[nt][3];
        }
        psa += __shfl_xor_sync(0xFFFFFFFF, psa, 1);
        psa += __shfl_xor_sync(0xFFFFFFFF, psa, 2);
        psb += __shfl_xor_sync(0xFFFFFFFF, psb, 1);
        psb += __shfl_xor_sync(0xFFFFFFFF, psb, 2);
        l0 = l0 * fa_ + psa; l1 = l1 * fb_ + psb;
        m0 = na; m1 = nb;
        #pragma unroll
        for (int nt = 0; nt < 16; nt++) {
            oacc[nt][0] *= fa_; oacc[nt][1] *= fa_;
            oacc[nt][2] *= fb_; oacc[nt][3] *= fb_;
        }
        // stage P (warp-local rows; tf32-rounded)
        #pragma unroll
        for (int nt = 0; nt < 16; nt++) {
            int cb = nt * 8 + 2 * qd;
            *(float2*)(prow + cb) =
                make_float2(tf32r(sacc[nt][0]), tf32r(sacc[nt][1]));
            *(float2*)(prow + 8 * FA_SROW + cb) =
                make_float2(tf32r(sacc[nt][2]), tf32r(sacc[nt][3]));
        }

        if (it + 1 < 16) cp_wait<1>(); else cp_wait<0>();   // V(it) complete
        __syncthreads();

        // ---- O += P @ V ----
        #pragma unroll
        for (int kk = 0; kk < 16; kk++) {
            const int colk = kk * 8 + qd;
            uint32_t pa[4];
            pa[0] = __float_as_uint(prow[colk]);
            pa[1] = __float_as_uint(prow[8 * FA_SROW + colk]);
            pa[2] = __float_as_uint(prow[colk + 4]);
            pa[3] = __float_as_uint(prow[8 * FA_SROW + colk + 4]);
            #pragma unroll
            for (int nt = 0; nt < 16; nt++) {
                uint32_t bf[2];
                const float* bp = sV + (nt * 8 + group) * FA_SROW + colk;
                bf[0] = __float_as_uint(bp[0]);
                bf[1] = __float_as_uint(bp[4]);
                mma_tf32(oacc[nt], pa, bf);
            }
        }
        __syncthreads();         // everyone done reading sV
        if (it + 1 < 16) {       // V(it+1) load overlaps next QK
            const float* Vn = Vg + (it + 1) * 128;
            #pragma unroll
            for (int i = 0; i < 16; i++) {
                int idx = i * 256 + tid;
                int r = idx >> 5, c = (idx & 31) * 4;
                cp16(uV + (uint32_t)(r * FA_SROW + c) * 4, Vn + (size_t)r * S_LEN + c);
            }
            cp_commit();
        }
    }

    // ---- finalize: O /= l, write att[b, q0+row, h*128+col] ----
    float inv0 = 1.0f / l0, inv1 = 1.0f / l1;
    int ra = q0 + wid * 16 + group;
    float* outa = att + (size_t)(b * S_LEN + ra) * D_MODEL + h * HDIM;
    float* outb = outa + 8 * (size_t)D_MODEL;
    #pragma unroll
    for (int nt = 0; nt < 16; nt++) {
        int cb = nt * 8 + 2 * qd;
        *(float2*)(outa + cb) =
            make_float2(tf32r(oacc[nt][0] * inv0), tf32r(oacc[nt][1] * inv0));
        *(float2*)(outb + cb) =
            make_float2(tf32r(oacc[nt][2] * inv1), tf32r(oacc[nt][3] * inv1));
    }
}

// ---------------------------------------------------------------------------
// Launch
// ---------------------------------------------------------------------------
extern "C" void kernel_launch(void* const* d_in, const int* in_sizes, int n_in,
                              void* d_out, int out_size) {
    const float* x  = (const float*)d_in[0];
    const float* Wq = (const float*)d_in[1];
    const float* bq = (const float*)d_in[2];
    const float* Wk = (const float*)d_in[3];
    const float* bk = (const float*)d_in[4];
    const float* Wv = (const float*)d_in[5];
    const float* bv = (const float*)d_in[6];
    const float* Wo = (const float*)d_in[7];
    const float* bo = (const float*)d_in[8];
    float* out = (float*)d_out;

    float *q, *k, *vt, *att, *wt;
    cudaGetSymbolAddress((void**)&q,   g_q);
    cudaGetSymbolAddress((void**)&k,   g_k);
    cudaGetSymbolAddress((void**)&vt,  g_vt);
    cudaGetSymbolAddress((void**)&att, g_att);
    cudaGetSymbolAddress((void**)&wt,  g_wt);
    float* wt0 = wt;
    float* wt1 = wt + (size_t)D_MODEL * D_MODEL;
    float* wt2 = wt + 2 * (size_t)D_MODEL * D_MODEL;
    float* wt3 = wt + 3 * (size_t)D_MODEL * D_MODEL;
    float* xr = att;   // att buffer reused as tf32-rounded x during projections

    cudaFuncSetAttribute((const void*)tc_gemm<0,0>,
                         cudaFuncAttributeMaxDynamicSharedMemorySize, GEMM_SMEM_SZ);
    cudaFuncSetAttribute((const void*)tc_gemm<1,1>,
                         cudaFuncAttributeMaxDynamicSharedMemorySize, GEMM_SMEM_SZ);
    cudaFuncSetAttribute((const void*)tc_gemm<2,1>,
                         cudaFuncAttributeMaxDynamicSharedMemorySize, GEMM_SMEM_SZ);
    cudaFuncSetAttribute((const void*)fa_kernel,
                         cudaFuncAttributeMaxDynamicSharedMemorySize, FA_SMEM_SZ);

    // 0. preprocessing
    dim3 tb(32, 8);
    dim3 tg(D_MODEL / 32, D_MODEL / 32);
    transpose_kernel<<<tg, tb>>>(Wq, wt0);
    transpose_kernel<<<tg, tb>>>(Wk, wt1);
    transpose_kernel<<<tg, tb>>>(Wv, wt2);
    transpose_kernel<<<tg, tb>>>(Wo, wt3);
    int nx = NB * S_LEN * D_MODEL;
    round_copy_kernel<<<(nx + 255) / 256, 256>>>(x, xr, nx);
    rope_tables_kernel<<<(S_LEN * HALF_HD + 255) / 256, 256>>>();

    // 1. projections: Q,K with fused RoPE; V with fused transpose
    dim3 gProj(D_MODEL / 128, (NB * S_LEN) / 128);      // (16, 32)
    tc_gemm<1,1><<<gProj, 256, GEMM_SMEM_SZ>>>(xr, D_MODEL, wt0, D_MODEL, q, D_MODEL,
                                               bq, D_MODEL, 1.0f);
    tc_gemm<1,1><<<gProj, 256, GEMM_SMEM_SZ>>>(xr, D_MODEL, wt1, D_MODEL, k, D_MODEL,
                                               bk, D_MODEL, 1.0f);
    tc_gemm<2,1><<<gProj, 256, GEMM_SMEM_SZ>>>(xr, D_MODEL, wt2, D_MODEL, vt, D_MODEL,
                                               bv, D_MODEL, 1.0f);

    // 2. fused attention (QK^T + softmax + PV), writes att (overwrites xr — safe)
    dim3 gFA(S_LEN / 128, BH);                          // (16, 32)
    fa_kernel<<<gFA, 256, FA_SMEM_SZ>>>(q, k, vt, att);

    // 3. out = att @ Wo + bo
    tc_gemm<0,0><<<gProj, 256, GEMM_SMEM_SZ>>>(att, D_MODEL, wt3, D_MODEL, out, D_MODEL,
                                               bo, D_MODEL, 1.0f);
}

// round 8
// speedup vs baseline: 3.9728x; 1.1656x over previous
#include <cuda_runtime.h>
#include <math.h>
#include <cstdint>

// Problem constants
#define S_LEN 2048
#define D_MODEL 2048
#define NB 2
#define NH 16
#define HDIM 128
#define BH (NB*NH)
#define HALF_HD 64

// ---------------------------------------------------------------------------
// Scratch
// ---------------------------------------------------------------------------
__device__ float g_q  [NB*S_LEN*D_MODEL];
__device__ float g_k  [NB*S_LEN*D_MODEL];
__device__ float g_vt [BH*HDIM*S_LEN];          // V^T per (b,h): [128][2048]
__device__ float g_att[NB*S_LEN*D_MODEL];       // doubles as tf32-rounded x
__device__ float g_wt [4*D_MODEL*D_MODEL];      // W^T (tf32-rounded)
__device__ float g_cos[S_LEN*HALF_HD];
__device__ float g_sin[S_LEN*HALF_HD];

// ---------------------------------------------------------------------------
// Helpers
// ---------------------------------------------------------------------------
__device__ __forceinline__ float tf32r(float x) {
    uint32_t u = __float_as_uint(x);
    asm("cvt.rna.tf32.f32 %0, %1;" : "=r"(u) : "r"(u));
    return __uint_as_float(u);
}

__device__ __forceinline__ uint32_t smem_u32(const void* p) {
    uint32_t a;
    asm("{ .reg .u64 t; cvta.to.shared.u64 t, %1; cvt.u32.u64 %0, t; }"
        : "=r"(a) : "l"(p));
    return a;
}

__device__ __forceinline__ void cp16(uint32_t dst, const float* src) {
    asm volatile("cp.async.cg.shared.global [%0], [%1], 16;" :: "r"(dst), "l"(src));
}
__device__ __forceinline__ void cp_commit() {
    asm volatile("cp.async.commit_group;");
}
template<int N>
__device__ __forceinline__ void cp_wait() {
    asm volatile("cp.async.wait_group %0;" :: "n"(N));
}

__device__ __forceinline__ void mma_tf32(float* c, const uint32_t* a, const uint32_t* b) {
    asm volatile(
        "mma.sync.aligned.m16n8k8.row.col.f32.tf32.tf32.f32 "
        "{%0,%1,%2,%3}, {%4,%5,%6,%7}, {%8,%9}, {%0,%1,%2,%3};"
        : "+f"(c[0]), "+f"(c[1]), "+f"(c[2]), "+f"(c[3])
        : "r"(a[0]), "r"(a[1]), "r"(a[2]), "r"(a[3]), "r"(b[0]), "r"(b[1]));
}

// ---------------------------------------------------------------------------
// RoPE tables
// ---------------------------------------------------------------------------
__global__ void rope_tables_kernel() {
    int idx = blockIdx.x * blockDim.x + threadIdx.x;
    if (idx >= S_LEN * HALF_HD) return;
    int s = idx / HALF_HD;
    int i = idx % HALF_HD;
    float inv = expf(-((float)(2 * i) / (float)HDIM) * logf(10000.0f));
    float f = (float)s * inv;
    g_cos[idx] = cosf(f);
    g_sin[idx] = sinf(f);
}

// ---------------------------------------------------------------------------
// x -> tf32-rounded copy
// ---------------------------------------------------------------------------
__global__ void round_copy_kernel(const float* __restrict__ in, float* __restrict__ out, int n) {
    int i = blockIdx.x * blockDim.x + threadIdx.x;
    if (i < n) out[i] = tf32r(in[i]);
}

// ---------------------------------------------------------------------------
// 4x 2048x2048 transpose with tf32 rounding (all W^T in one launch, z selects)
// ---------------------------------------------------------------------------
__global__ void transpose4_kernel(const float* __restrict__ Wq, const float* __restrict__ Wk,
                                  const float* __restrict__ Wv, const float* __restrict__ Wo,
                                  float* __restrict__ wt) {
    __shared__ float t[32][33];
    const float* in = (blockIdx.z == 0) ? Wq : (blockIdx.z == 1) ? Wk
                     : (blockIdx.z == 2) ? Wv : Wo;
    float* out = wt + (size_t)blockIdx.z * D_MODEL * D_MODEL;
    int x = blockIdx.x * 32 + threadIdx.x;
    int y = blockIdx.y * 32 + threadIdx.y;
    #pragma unroll
    for (int j = 0; j < 32; j += 8)
        t[threadIdx.y + j][threadIdx.x] = tf32r(in[(size_t)(y + j) * D_MODEL + x]);
    __syncthreads();
    x = blockIdx.y * 32 + threadIdx.x;
    y = blockIdx.x * 32 + threadIdx.y;
    #pragma unroll
    for (int j = 0; j < 32; j += 8)
        out[(size_t)(y + j) * D_MODEL + x] = t[threadIdx.x][threadIdx.y + j];
}

// ---------------------------------------------------------------------------
// Shared GEMM mainloop: 128x128 CTA tile, BK=32, K=2048, 128 threads (4 warps),
// warp tile 64x64 (2x2). A: [128 rows, 2048] row-major; B: [128 rows, 2048]
// K-major. Result staged into sbase as Cs[128][CSTR].
// ---------------------------------------------------------------------------
#define SROW 36
#define TILE_F (128*SROW)
#define GEMM_SMEM_SZ (2*2*TILE_F*4)     // 73728 bytes
#define CSTR 132

__device__ __forceinline__ void gemm_128x128(
    const float* __restrict__ Ag, const float* __restrict__ Bg,
    float* sbase, uint32_t s_u32, int tid)
{
    const int wid = tid >> 5;
    const int lane = tid & 31;
    const int group = lane >> 2;
    const int qd = lane & 3;
    const int wm = (wid >> 1) * 64;
    const int wn = (wid & 1) * 64;
    const int lr = tid >> 3;            // 0..15
    const int lc4 = (tid & 7) * 4;

    float acc[4][8][4];
    #pragma unroll
    for (int mt = 0; mt < 4; mt++)
        #pragma unroll
        for (int nt = 0; nt < 8; nt++)
            #pragma unroll
            for (int i = 0; i < 4; i++) acc[mt][nt][i] = 0.0f;

    // prologue: chunk 0
    {
        uint32_t sa = s_u32;
        uint32_t sb = s_u32 + TILE_F * 4;
        #pragma unroll
        for (int i = 0; i < 8; i++) {
            int r = i * 16 + lr;
            uint32_t so = (uint32_t)(r * SROW + lc4) * 4;
            cp16(sa + so, Ag + (size_t)r * D_MODEL + lc4);
            cp16(sb + so, Bg + (size_t)r * D_MODEL + lc4);
        }
        cp_commit();
    }

    for (int ch = 0; ch < 64; ch++) {
        const int st = ch & 1;
        if (ch + 1 < 64) {
            const int k0 = (ch + 1) << 5;
            uint32_t sa = s_u32 + (uint32_t)((ch + 1) & 1) * (2 * TILE_F * 4);
            uint32_t sb = sa + TILE_F * 4;
            #pragma unroll
            for (int i = 0; i < 8; i++) {
                int r = i * 16 + lr;
                uint32_t so = (uint32_t)(r * SROW + lc4) * 4;
                cp16(sa + so, Ag + (size_t)r * D_MODEL + k0 + lc4);
                cp16(sb + so, Bg + (size_t)r * D_MODEL + k0 + lc4);
            }
            cp_commit();
            cp_wait<1>();
        } else {
            cp_wait<0>();
        }
        __syncthreads();

        const float* As = sbase + st * 2 * TILE_F;
        const float* Bs = As + TILE_F;

        #pragma unroll
        for (int kk = 0; kk < 4; kk++) {
            const int colk = kk * 8 + qd;
            uint32_t af[4][4], bf[8][2];
            #pragma unroll
            for (int mt = 0; mt < 4; mt++) {
                int r0 = wm + mt * 16 + group;
                af[mt][0] = __float_as_uint(As[r0 * SROW + colk]);
                af[mt][1] = __float_as_uint(As[(r0 + 8) * SROW + colk]);
                af[mt][2] = __float_as_uint(As[r0 * SROW + colk + 4]);
                af[mt][3] = __float_as_uint(As[(r0 + 8) * SROW + colk + 4]);
            }
            #pragma unroll
            for (int nt = 0; nt < 8; nt++) {
                int bn = wn + nt * 8 + group;
                bf[nt][0] = __float_as_uint(Bs[bn * SROW + colk]);
                bf[nt][1] = __float_as_uint(Bs[bn * SROW + colk + 4]);
            }
            #pragma unroll
            for (int mt = 0; mt < 4; mt++)
                #pragma unroll
                for (int nt = 0; nt < 8; nt++)
                    mma_tf32(acc[mt][nt], af[mt], bf[nt]);
        }
        __syncthreads();
    }

    // stage C tile in smem
    float* Cs = sbase;
    #pragma unroll
    for (int mt = 0; mt < 4; mt++) {
        int r0 = wm + mt * 16 + group;
        #pragma unroll
        for (int nt = 0; nt < 8; nt++) {
            int cb = wn + nt * 8 + 2 * qd;
            Cs[r0 * CSTR + cb]           = acc[mt][nt][0];
            Cs[r0 * CSTR + cb + 1]       = acc[mt][nt][1];
            Cs[(r0 + 8) * CSTR + cb]     = acc[mt][nt][2];
            Cs[(r0 + 8) * CSTR + cb + 1] = acc[mt][nt][3];
        }
    }
    __syncthreads();
}

// ---------------------------------------------------------------------------
// QKV combined projection: grid (16, 32, 3). z=0: Q (RoPE), z=1: K (RoPE),
// z=2: V (transposed write). Outputs tf32-rounded.
// ---------------------------------------------------------------------------
__global__ void __launch_bounds__(128, 2)
tc_gemm_qkv(const float* __restrict__ A,
            const float* __restrict__ W0, const float* __restrict__ W1,
            const float* __restrict__ W2,
            const float* __restrict__ b0, const float* __restrict__ b1,
            const float* __restrict__ b2,
            float* __restrict__ Cq, float* __restrict__ Ck, float* __restrict__ Cv)
{
    extern __shared__ char smem_raw[];
    float* sbase = (float*)smem_raw;
    const uint32_t s_u32 = smem_u32(smem_raw);
    const int tid = threadIdx.x;
    const int z = blockIdx.z;
    const int m0 = blockIdx.y * 128;
    const int n0 = blockIdx.x * 128;

    const float* W = (z == 0) ? W0 : (z == 1) ? W1 : W2;
    const float* bias = (z == 0) ? b0 : (z == 1) ? b1 : b2;

    gemm_128x128(A + (size_t)m0 * D_MODEL, W + (size_t)n0 * D_MODEL,
                 sbase, s_u32, tid);
    const float* Cs = sbase;

    if (z < 2) {
        // RoPE epilogue into q or k: [b,s,2048] layout, pair (ci, ci+64)
        float* C = (z == 0) ? Cq : Ck;
        #pragma unroll
        for (int i = 0; i < 64; i++) {
            int flat = i * 128 + tid;
            int row = flat >> 6;
            int ci = flat & 63;
            float v1 = Cs[row * CSTR + ci]      + __ldg(bias + n0 + ci);
            float v2 = Cs[row * CSTR + ci + 64] + __ldg(bias + n0 + ci + 64);
            int s = (m0 + row) & (S_LEN - 1);
            float cv = g_cos[s * HALF_HD + ci];
            float sv = g_sin[s * HALF_HD + ci];
            float o1 = v1 * cv - v2 * sv;
            float o2 = v1 * sv + v2 * cv;
            float* dst = C + (size_t)(m0 + row) * D_MODEL + n0 + ci;
            dst[0]  = tf32r(o1);
            dst[64] = tf32r(o2);
        }
    } else {
        // V^T epilogue: vt[((b*16+h)*128 + d)*S_LEN + s]
        const int h = n0 >> 7;
        #pragma unroll
        for (int i = 0; i < 128; i++) {
            int flat = i * 128 + tid;
            int sl = flat & 127;
            int d = flat >> 7;
            float v = Cs[sl * CSTR + d] + __ldg(bias + n0 + d);
            int b = (m0 + sl) >> 11;
            int s = (m0 + sl) & (S_LEN - 1);
            Cv[((size_t)(b * NH + h) * HDIM + d) * S_LEN + s] = tf32r(v);
        }
    }
}

// ---------------------------------------------------------------------------
// Output projection: plain bias epilogue, full fp32 output.
// ---------------------------------------------------------------------------
__global__ void __launch_bounds__(128, 2)
tc_gemm_o(const float* __restrict__ A, const float* __restrict__ W,
          const float* __restrict__ bias, float* __restrict__ C)
{
    extern __shared__ char smem_raw[];
    float* sbase = (float*)smem_raw;
    const uint32_t s_u32 = smem_u32(smem_raw);
    const int tid = threadIdx.x;
    const int m0 = blockIdx.y * 128;
    const int n0 = blockIdx.x * 128;

    gemm_128x128(A + (size_t)m0 * D_MODEL, W + (size_t)n0 * D_MODEL,
                 sbase, s_u32, tid);
    const float* Cs = sbase;

    const int col4 = (tid & 31) * 4;
    float bv[4];
    bv[0] = __ldg(bias + n0 + col4);
    bv[1] = __ldg(bias + n0 + col4 + 1);
    bv[2] = __ldg(bias + n0 + col4 + 2);
    bv[3] = __ldg(bias + n0 + col4 + 3);
    #pragma unroll
    for (int i = 0; i < 32; i++) {
        int row = (tid >> 5) + i * 4;
        const float* src = Cs + row * CSTR + col4;
        float4 v;
        v.x = src[0] + bv[0];
        v.y = src[1] + bv[1];
        v.z = src[2] + bv[2];
        v.w = src[3] + bv[3];
        *(float4*)(C + (size_t)(m0 + row) * D_MODEL + n0 + col4) = v;
    }
}

// ---------------------------------------------------------------------------
// Flash attention: per (q-tile 128, bh). 256 threads, 8 warps x (16 rows, 128 cols).
// Online softmax; K/V tiles pipelined across phases. (Unchanged from R6 — passing.)
// ---------------------------------------------------------------------------
#define FA_SROW 132
#define FA_TILE (128*FA_SROW)
#define FA_SMEM_SZ (3*FA_TILE*4)      // 202752 bytes

__global__ void __launch_bounds__(256, 1)
fa_kernel(const float* __restrict__ q, const float* __restrict__ k,
          const float* __restrict__ vt, float* __restrict__ att)
{
    extern __shared__ float sm[];
    float* sQP = sm;
    float* sK  = sm + FA_TILE;
    float* sV  = sm + 2 * FA_TILE;
    const uint32_t uQP = smem_u32(sQP);
    const uint32_t uK  = smem_u32(sK);
    const uint32_t uV  = smem_u32(sV);

    const int tid = threadIdx.x;
    const int wid = tid >> 5;
    const int lane = tid & 31;
    const int group = lane >> 2;
    const int qd = lane & 3;
    const int bh = blockIdx.y;
    const int b = bh >> 4, h = bh & 15;
    const int q0 = blockIdx.x * 128;

    const float* Qg = q + ((size_t)(b * S_LEN + q0)) * D_MODEL + h * HDIM;
    const float* Kg = k + ((size_t)b * S_LEN) * D_MODEL + h * HDIM;
    const float* Vg = vt + (size_t)bh * HDIM * S_LEN;

    #pragma unroll
    for (int i = 0; i < 16; i++) {
        int idx = i * 256 + tid;
        int r = idx >> 5, c = (idx & 31) * 4;
        cp16(uQP + (uint32_t)(r * FA_SROW + c) * 4, Qg + (size_t)r * D_MODEL + c);
    }
    cp_commit();
    #pragma unroll
    for (int i = 0; i < 16; i++) {
        int idx = i * 256 + tid;
        int r = idx >> 5, c = (idx & 31) * 4;
        cp16(uK + (uint32_t)(r * FA_SROW + c) * 4, Kg + (size_t)r * D_MODEL + c);
    }
    cp_commit();
    cp_wait<1>();
    __syncthreads();

    uint32_t qa[16][4];
    {
        const float* base = sQP + (wid * 16 + group) * FA_SROW;
        #pragma unroll
        for (int kk = 0; kk < 16; kk++) {
            qa[kk][0] = __float_as_uint(base[kk * 8 + qd]);
            qa[kk][1] = __float_as_uint(base[8 * FA_SROW + kk * 8 + qd]);
            qa[kk][2] = __float_as_uint(base[kk * 8 + qd + 4]);
            qa[kk][3] = __float_as_uint(base[8 * FA_SROW + kk * 8 + qd + 4]);
        }
    }
    __syncthreads();
    #pragma unroll
    for (int i = 0; i < 16; i++) {
        int idx = i * 256 + tid;
        int r = idx >> 5, c = (idx & 31) * 4;
        cp16(uV + (uint32_t)(r * FA_SROW + c) * 4, Vg + (size_t)r * S_LEN + c);
    }
    cp_commit();

    const float alpha = 0.08838834764831843f;
    float m0 = -1e30f, m1 = -1e30f, l0 = 0.0f, l1 = 0.0f;
    float oacc[16][4];
    #pragma unroll
    for (int nt = 0; nt < 16; nt++)
        #pragma unroll
        for (int i = 0; i < 4; i++) oacc[nt][i] = 0.0f;

    float* prow = sQP + (wid * 16 + group) * FA_SROW;

    for (int it = 0; it < 16; it++) {
        cp_wait<1>();
        __syncthreads();

        float sacc[16][4];
        #pragma unroll
        for (int nt = 0; nt < 16; nt++)
            #pragma unroll
            for (int i = 0; i < 4; i++) sacc[nt][i] = 0.0f;

        #pragma unroll
        for (int kk = 0; kk < 16; kk++) {
            const int colk = kk * 8 + qd;
            #pragma unroll
            for (int nt = 0; nt < 16; nt++) {
                uint32_t bf[2];
                const float* bp = sK + (nt * 8 + group) * FA_SROW + colk;
                bf[0] = __float_as_uint(bp[0]);
                bf[1] = __float_as_uint(bp[4]);
                mma_tf32(sacc[nt], qa[kk], bf);
            }
        }
        __syncthreads();
        if (it + 1 < 16) {
            const float* Kn = Kg + (size_t)(it + 1) * 128 * D_MODEL;
            #pragma unroll
            for (int i = 0; i < 16; i++) {
                int idx = i * 256 + tid;
                int r = idx >> 5, c = (idx & 31) * 4;
                cp16(uK + (uint32_t)(r * FA_SROW + c) * 4, Kn + (size_t)r * D_MODEL + c);
            }
            cp_commit();
        }

        float mxa = -1e30f, mxb = -1e30f;
        #pragma unroll
        for (int nt = 0; nt < 16; nt++) {
            sacc[nt][0] *= alpha; sacc[nt][1] *= alpha;
            sacc[nt][2] *= alpha; sacc[nt][3] *= alpha;
            mxa = fmaxf(mxa, fmaxf(sacc[nt][0], sacc[nt][1]));
            mxb = fmaxf(mxb, fmaxf(sacc[nt][2], sacc[nt][3]));
        }
        mxa = fmaxf(mxa, __shfl_xor_sync(0xFFFFFFFF, mxa, 1));
        mxa = fmaxf(mxa, __shfl_xor_sync(0xFFFFFFFF, mxa, 2));
        mxb = fmaxf(mxb, __shfl_xor_sync(0xFFFFFFFF, mxb, 1));
        mxb = fmaxf(mxb, __shfl_xor_sync(0xFFFFFFFF, mxb, 2));
        float na = fmaxf(m0, mxa), nb = fmaxf(m1, mxb);
        float fa_ = __expf(m0 - na), fb_ = __expf(m1 - nb);
        float psa = 0.0f, psb = 0.0f;
        #pragma unroll
        for (int nt = 0; nt < 16; nt++) {
            sacc[nt][0] = __expf(sacc[nt][0] - na);
            sacc[nt][1] = __expf(sacc[nt][1] - na);
            sacc[nt][2] = __expf(sacc[nt][2] - nb);
            sacc[nt][3] = __expf(sacc[nt][3] - nb);
            psa += sacc[nt][0] + sacc[nt][1];
            psb += sacc[nt][2] + sacc[nt][3];
        }
        psa += __shfl_xor_sync(0xFFFFFFFF, psa, 1);
        psa += __shfl_xor_sync(0xFFFFFFFF, psa, 2);
        psb += __shfl_xor_sync(0xFFFFFFFF, psb, 1);
        psb += __shfl_xor_sync(0xFFFFFFFF, psb, 2);
        l0 = l0 * fa_ + psa; l1 = l1 * fb_ + psb;
        m0 = na; m1 = nb;
        #pragma unroll
        for (int nt = 0; nt < 16; nt++) {
            oacc[nt][0] *= fa_; oacc[nt][1] *= fa_;
            oacc[nt][2] *= fb_; oacc[nt][3] *= fb_;
        }
        #pragma unroll
        for (int nt = 0; nt < 16; nt++) {
            int cb = nt * 8 + 2 * qd;
            *(float2*)(prow + cb) =
                make_float2(tf32r(sacc[nt][0]), tf32r(sacc[nt][1]));
            *(float2*)(prow + 8 * FA_SROW + cb) =
                make_float2(tf32r(sacc[nt][2]), tf32r(sacc[nt][3]));
        }

        if (it + 1 < 16) cp_wait<1>(); else cp_wait<0>();
        __syncthreads();

        #pragma unroll
        for (int kk = 0; kk < 16; kk++) {
            const int colk = kk * 8 + qd;
            uint32_t pa[4];
            pa[0] = __float_as_uint(prow[colk]);
            pa[1] = __float_as_uint(prow[8 * FA_SROW + colk]);
            pa[2] = __float_as_uint(prow[colk + 4]);
            pa[3] = __float_as_uint(prow[8 * FA_SROW + colk + 4]);
            #pragma unroll
            for (int nt = 0; nt < 16; nt++) {
                uint32_t bf[2];
                const float* bp = sV + (nt * 8 + group) * FA_SROW + colk;
                bf[0] = __float_as_uint(bp[0]);
                bf[1] = __float_as_uint(bp[4]);
                mma_tf32(oacc[nt], pa, bf);
            }
        }
        __syncthreads();
        if (it + 1 < 16) {
            const float* Vn = Vg + (it + 1) * 128;
            #pragma unroll
            for (int i = 0; i < 16; i++) {
                int idx = i * 256 + tid;
                int r = idx >> 5, c = (idx & 31) * 4;
                cp16(uV + (uint32_t)(r * FA_SROW + c) * 4, Vn + (size_t)r * S_LEN + c);
            }
            cp_commit();
        }
    }

    float inv0 = 1.0f / l0, inv1 = 1.0f / l1;
    int ra = q0 + wid * 16 + group;
    float* outa = att + (size_t)(b * S_LEN + ra) * D_MODEL + h * HDIM;
    float* outb = outa + 8 * (size_t)D_MODEL;
    #pragma unroll
    for (int nt = 0; nt < 16; nt++) {
        int cb = nt * 8 + 2 * qd;
        *(float2*)(outa + cb) =
            make_float2(tf32r(oacc[nt][0] * inv0), tf32r(oacc[nt][1] * inv0));
        *(float2*)(outb + cb) =
            make_float2(tf32r(oacc[nt][2] * inv1), tf32r(oacc[nt][3] * inv1));
    }
}

// ---------------------------------------------------------------------------
// Launch
// ---------------------------------------------------------------------------
extern "C" void kernel_launch(void* const* d_in, const int* in_sizes, int n_in,
                              void* d_out, int out_size) {
    const float* x  = (const float*)d_in[0];
    const float* Wq = (const float*)d_in[1];
    const float* bq = (const float*)d_in[2];
    const float* Wk = (const float*)d_in[3];
    const float* bk = (const float*)d_in[4];
    const float* Wv = (const float*)d_in[5];
    const float* bv = (const float*)d_in[6];
    const float* Wo = (const float*)d_in[7];
    const float* bo = (const float*)d_in[8];
    float* out = (float*)d_out;

    float *q, *k, *vt, *att, *wt;
    cudaGetSymbolAddress((void**)&q,   g_q);
    cudaGetSymbolAddress((void**)&k,   g_k);
    cudaGetSymbolAddress((void**)&vt,  g_vt);
    cudaGetSymbolAddress((void**)&att, g_att);
    cudaGetSymbolAddress((void**)&wt,  g_wt);
    float* wt0 = wt;
    float* wt1 = wt + (size_t)D_MODEL * D_MODEL;
    float* wt2 = wt + 2 * (size_t)D_MODEL * D_MODEL;
    float* wt3 = wt + 3 * (size_t)D_MODEL * D_MODEL;
    float* xr = att;   // att buffer reused as tf32-rounded x during projections

    cudaFuncSetAttribute((const void*)tc_gemm_qkv,
                         cudaFuncAttributeMaxDynamicSharedMemorySize, GEMM_SMEM_SZ);
    cudaFuncSetAttribute((const void*)tc_gemm_o,
                         cudaFuncAttributeMaxDynamicSharedMemorySize, GEMM_SMEM_SZ);
    cudaFuncSetAttribute((const void*)fa_kernel,
                         cudaFuncAttributeMaxDynamicSharedMemorySize, FA_SMEM_SZ);

    // 0. preprocessing: all W^T in one launch; x rounded; RoPE tables
    dim3 tb(32, 8);
    dim3 tg4(D_MODEL / 32, D_MODEL / 32, 4);
    transpose4_kernel<<<tg4, tb>>>(Wq, Wk, Wv, Wo, wt);
    int nx = NB * S_LEN * D_MODEL;
    round_copy_kernel<<<(nx + 255) / 256, 256>>>(x, xr, nx);
    rope_tables_kernel<<<(S_LEN * HALF_HD + 255) / 256, 256>>>();

    // 1. QKV projections in one launch (z=0:Q+RoPE, 1:K+RoPE, 2:V^T)
    dim3 gQKV(D_MODEL / 128, (NB * S_LEN) / 128, 3);    // (16, 32, 3)
    tc_gemm_qkv<<<gQKV, 128, GEMM_SMEM_SZ>>>(xr, wt0, wt1, wt2, bq, bk, bv,
                                             q, k, vt);

    // 2. fused attention (QK^T + softmax + PV), writes att (overwrites xr — safe)
    dim3 gFA(S_LEN / 128, BH);                          // (16, 32)
    fa_kernel<<<gFA, 256, FA_SMEM_SZ>>>(q, k, vt, att);

    // 3. out = att @ Wo + bo
    dim3 gO(D_MODEL / 128, (NB * S_LEN) / 128);         // (16, 32)
    tc_gemm_o<<<gO, 128, GEMM_SMEM_SZ>>>(att, wt3, bo, out);
}

// round 9
// speedup vs baseline: 3.9729x; 1.0000x over previous
#include <cuda_runtime.h>
#include <math.h>
#include <cstdint>

// Problem constants
#define S_LEN 2048
#define D_MODEL 2048
#define NB 2
#define NH 16
#define HDIM 128
#define BH (NB*NH)
#define HALF_HD 64

// ---------------------------------------------------------------------------
// Scratch
// ---------------------------------------------------------------------------
__device__ float g_q  [NB*S_LEN*D_MODEL];
__device__ float g_k  [NB*S_LEN*D_MODEL];
__device__ float g_vt [BH*HDIM*S_LEN];          // V^T per (b,h): [128][2048]
__device__ float g_att[NB*S_LEN*D_MODEL];       // doubles as tf32-rounded x
__device__ float g_wt [4*D_MODEL*D_MODEL];      // W^T (tf32-rounded)
__device__ float g_cos[S_LEN*HALF_HD];
__device__ float g_sin[S_LEN*HALF_HD];

// ---------------------------------------------------------------------------
// Helpers
// ---------------------------------------------------------------------------
__device__ __forceinline__ float tf32r(float x) {
    uint32_t u = __float_as_uint(x);
    asm("cvt.rna.tf32.f32 %0, %1;" : "=r"(u) : "r"(u));
    return __uint_as_float(u);
}

__device__ __forceinline__ uint32_t smem_u32(const void* p) {
    uint32_t a;
    asm("{ .reg .u64 t; cvta.to.shared.u64 t, %1; cvt.u32.u64 %0, t; }"
        : "=r"(a) : "l"(p));
    return a;
}

__device__ __forceinline__ void cp16(uint32_t dst, const float* src) {
    asm volatile("cp.async.cg.shared.global [%0], [%1], 16;" :: "r"(dst), "l"(src));
}
__device__ __forceinline__ void cp_commit() {
    asm volatile("cp.async.commit_group;");
}
template<int N>
__device__ __forceinline__ void cp_wait() {
    asm volatile("cp.async.wait_group %0;" :: "n"(N));
}

__device__ __forceinline__ void mma_tf32(float* c, const uint32_t* a, const uint32_t* b) {
    asm volatile(
        "mma.sync.aligned.m16n8k8.row.col.f32.tf32.tf32.f32 "
        "{%0,%1,%2,%3}, {%4,%5,%6,%7}, {%8,%9}, {%0,%1,%2,%3};"
        : "+f"(c[0]), "+f"(c[1]), "+f"(c[2]), "+f"(c[3])
        : "r"(a[0]), "r"(a[1]), "r"(a[2]), "r"(a[3]), "r"(b[0]), "r"(b[1]));
}

// ---------------------------------------------------------------------------
// RoPE tables
// ---------------------------------------------------------------------------
__global__ void rope_tables_kernel() {
    int idx = blockIdx.x * blockDim.x + threadIdx.x;
    if (idx >= S_LEN * HALF_HD) return;
    int s = idx / HALF_HD;
    int i = idx % HALF_HD;
    float inv = expf(-((float)(2 * i) / (float)HDIM) * logf(10000.0f));
    float f = (float)s * inv;
    g_cos[idx] = cosf(f);
    g_sin[idx] = sinf(f);
}

// ---------------------------------------------------------------------------
// x -> tf32-rounded copy
// ---------------------------------------------------------------------------
__global__ void round_copy_kernel(const float* __restrict__ in, float* __restrict__ out, int n) {
    int i = blockIdx.x * blockDim.x + threadIdx.x;
    if (i < n) out[i] = tf32r(in[i]);
}

// ---------------------------------------------------------------------------
// 4x 2048x2048 transpose with tf32 rounding (all W^T in one launch, z selects)
// ---------------------------------------------------------------------------
__global__ void transpose4_kernel(const float* __restrict__ Wq, const float* __restrict__ Wk,
                                  const float* __restrict__ Wv, const float* __restrict__ Wo,
                                  float* __restrict__ wt) {
    __shared__ float t[32][33];
    const float* in = (blockIdx.z == 0) ? Wq : (blockIdx.z == 1) ? Wk
                     : (blockIdx.z == 2) ? Wv : Wo;
    float* out = wt + (size_t)blockIdx.z * D_MODEL * D_MODEL;
    int x = blockIdx.x * 32 + threadIdx.x;
    int y = blockIdx.y * 32 + threadIdx.y;
    #pragma unroll
    for (int j = 0; j < 32; j += 8)
        t[threadIdx.y + j][threadIdx.x] = tf32r(in[(size_t)(y + j) * D_MODEL + x]);
    __syncthreads();
    x = blockIdx.y * 32 + threadIdx.x;
    y = blockIdx.x * 32 + threadIdx.y;
    #pragma unroll
    for (int j = 0; j < 32; j += 8)
        out[(size_t)(y + j) * D_MODEL + x] = t[threadIdx.x][threadIdx.y + j];
}

// ---------------------------------------------------------------------------
// Shared GEMM mainloop: 128x128 CTA tile, BK=32, K=2048, 128 threads (4 warps),
// warp tile 64x64 (2x2). 3-stage cp.async pipeline, ONE barrier per chunk;
// loads issued 2 chunks ahead. Result staged into sbase as Cs[128][CSTR].
// ---------------------------------------------------------------------------
#define SROW 36
#define TILE_F (128*SROW)
#define NSTAGE 3
#define GEMM_SMEM_SZ (NSTAGE*2*TILE_F*4)   // 110592 bytes
#define CSTR 132

__device__ __forceinline__ void gemm_128x128(
    const float* __restrict__ Ag, const float* __restrict__ Bg,
    float* sbase, uint32_t s_u32, int tid)
{
    const int wid = tid >> 5;
    const int lane = tid & 31;
    const int group = lane >> 2;
    const int qd = lane & 3;
    const int wm = (wid >> 1) * 64;
    const int wn = (wid & 1) * 64;
    const int lr = tid >> 3;            // 0..15
    const int lc4 = (tid & 7) * 4;

    float acc[4][8][4];
    #pragma unroll
    for (int mt = 0; mt < 4; mt++)
        #pragma unroll
        for (int nt = 0; nt < 8; nt++)
            #pragma unroll
            for (int i = 0; i < 4; i++) acc[mt][nt][i] = 0.0f;

    // prologue: chunks 0 and 1 into stages 0 and 1
    #pragma unroll
    for (int pc = 0; pc < 2; pc++) {
        uint32_t sa = s_u32 + (uint32_t)pc * (2 * TILE_F * 4);
        uint32_t sb = sa + TILE_F * 4;
        const int k0 = pc << 5;
        #pragma unroll
        for (int i = 0; i < 8; i++) {
            int r = i * 16 + lr;
            uint32_t so = (uint32_t)(r * SROW + lc4) * 4;
            cp16(sa + so, Ag + (size_t)r * D_MODEL + k0 + lc4);
            cp16(sb + so, Bg + (size_t)r * D_MODEL + k0 + lc4);
        }
        cp_commit();
    }

    int stage = 0;                       // = ch % 3
    int lstage = 2;                      // = (ch+2) % 3
    for (int ch = 0; ch < 64; ch++) {
        if (ch < 63) cp_wait<1>(); else cp_wait<0>();
        __syncthreads();

        // issue chunk ch+2 into stage (ch+2)%3 (last read at ch-1, sealed above)
        if (ch + 2 < 64) {
            const int k0 = (ch + 2) << 5;
            uint32_t sa = s_u32 + (uint32_t)lstage * (2 * TILE_F * 4);
            uint32_t sb = sa + TILE_F * 4;
            #pragma unroll
            for (int i = 0; i < 8; i++) {
                int r = i * 16 + lr;
                uint32_t so = (uint32_t)(r * SROW + lc4) * 4;
                cp16(sa + so, Ag + (size_t)r * D_MODEL + k0 + lc4);
                cp16(sb + so, Bg + (size_t)r * D_MODEL + k0 + lc4);
            }
            cp_commit();
        }

        const float* As = sbase + stage * 2 * TILE_F;
        const float* Bs = As + TILE_F;

        #pragma unroll
        for (int kk = 0; kk < 4; kk++) {
            const int colk = kk * 8 + qd;
            uint32_t af[4][4], bf[8][2];
            #pragma unroll
            for (int mt = 0; mt < 4; mt++) {
                int r0 = wm + mt * 16 + group;
                af[mt][0] = __float_as_uint(As[r0 * SROW + colk]);
                af[mt][1] = __float_as_uint(As[(r0 + 8) * SROW + colk]);
                af[mt][2] = __float_as_uint(As[r0 * SROW + colk + 4]);
                af[mt][3] = __float_as_uint(As[(r0 + 8) * SROW + colk + 4]);
            }
            #pragma unroll
            for (int nt = 0; nt < 8; nt++) {
                int bn = wn + nt * 8 + group;
                bf[nt][0] = __float_as_uint(Bs[bn * SROW + colk]);
                bf[nt][1] = __float_as_uint(Bs[bn * SROW + colk + 4]);
            }
            #pragma unroll
            for (int mt = 0; mt < 4; mt++)
                #pragma unroll
                for (int nt = 0; nt < 8; nt++)
                    mma_tf32(acc[mt][nt], af[mt], bf[nt]);
        }

        stage = (stage == 2) ? 0 : stage + 1;
        lstage = (lstage == 2) ? 0 : lstage + 1;
    }
    __syncthreads();                     // seal mainloop before Cs overwrite

    // stage C tile in smem
    float* Cs = sbase;
    #pragma unroll
    for (int mt = 0; mt < 4; mt++) {
        int r0 = wm + mt * 16 + group;
        #pragma unroll
        for (int nt = 0; nt < 8; nt++) {
            int cb = wn + nt * 8 + 2 * qd;
            Cs[r0 * CSTR + cb]           = acc[mt][nt][0];
            Cs[r0 * CSTR + cb + 1]       = acc[mt][nt][1];
            Cs[(r0 + 8) * CSTR + cb]     = acc[mt][nt][2];
            Cs[(r0 + 8) * CSTR + cb + 1] = acc[mt][nt][3];
        }
    }
    __syncthreads();
}

// ---------------------------------------------------------------------------
// QKV combined projection: grid (16, 32, 3). z=0: Q (RoPE), z=1: K (RoPE),
// z=2: V (transposed write). Outputs tf32-rounded.
// ---------------------------------------------------------------------------
__global__ void __launch_bounds__(128, 2)
tc_gemm_qkv(const float* __restrict__ A,
            const float* __restrict__ W0, const float* __restrict__ W1,
            const float* __restrict__ W2,
            const float* __restrict__ b0, const float* __restrict__ b1,
            const float* __restrict__ b2,
            float* __restrict__ Cq, float* __restrict__ Ck, float* __restrict__ Cv)
{
    extern __shared__ char smem_raw[];
    float* sbase = (float*)smem_raw;
    const uint32_t s_u32 = smem_u32(smem_raw);
    const int tid = threadIdx.x;
    const int z = blockIdx.z;
    const int m0 = blockIdx.y * 128;
    const int n0 = blockIdx.x * 128;

    const float* W = (z == 0) ? W0 : (z == 1) ? W1 : W2;
    const float* bias = (z == 0) ? b0 : (z == 1) ? b1 : b2;

    gemm_128x128(A + (size_t)m0 * D_MODEL, W + (size_t)n0 * D_MODEL,
                 sbase, s_u32, tid);
    const float* Cs = sbase;

    if (z < 2) {
        // RoPE epilogue into q or k: [b,s,2048] layout, pair (ci, ci+64)
        float* C = (z == 0) ? Cq : Ck;
        #pragma unroll
        for (int i = 0; i < 64; i++) {
            int flat = i * 128 + tid;
            int row = flat >> 6;
            int ci = flat & 63;
            float v1 = Cs[row * CSTR + ci]      + __ldg(bias + n0 + ci);
            float v2 = Cs[row * CSTR + ci + 64] + __ldg(bias + n0 + ci + 64);
            int s = (m0 + row) & (S_LEN - 1);
            float cv = g_cos[s * HALF_HD + ci];
            float sv = g_sin[s * HALF_HD + ci];
            float o1 = v1 * cv - v2 * sv;
            float o2 = v1 * sv + v2 * cv;
            float* dst = C + (size_t)(m0 + row) * D_MODEL + n0 + ci;
            dst[0]  = tf32r(o1);
            dst[64] = tf32r(o2);
        }
    } else {
        // V^T epilogue: vt[((b*16+h)*128 + d)*S_LEN + s]
        const int h = n0 >> 7;
        #pragma unroll
        for (int i = 0; i < 128; i++) {
            int flat = i * 128 + tid;
            int sl = flat & 127;
            int d = flat >> 7;
            float v = Cs[sl * CSTR + d] + __ldg(bias + n0 + d);
            int b = (m0 + sl) >> 11;
            int s = (m0 + sl) & (S_LEN - 1);
            Cv[((size_t)(b * NH + h) * HDIM + d) * S_LEN + s] = tf32r(v);
        }
    }
}

// ---------------------------------------------------------------------------
// Output projection: plain bias epilogue, full fp32 output.
// ---------------------------------------------------------------------------
__global__ void __launch_bounds__(128, 2)
tc_gemm_o(const float* __restrict__ A, const float* __restrict__ W,
          const float* __restrict__ bias, float* __restrict__ C)
{
    extern __shared__ char smem_raw[];
    float* sbase = (float*)smem_raw;
    const uint32_t s_u32 = smem_u32(smem_raw);
    const int tid = threadIdx.x;
    const int m0 = blockIdx.y * 128;
    const int n0 = blockIdx.x * 128;

    gemm_128x128(A + (size_t)m0 * D_MODEL, W + (size_t)n0 * D_MODEL,
                 sbase, s_u32, tid);
    const float* Cs = sbase;

    const int col4 = (tid & 31) * 4;
    float bv[4];
    bv[0] = __ldg(bias + n0 + col4);
    bv[1] = __ldg(bias + n0 + col4 + 1);
    bv[2] = __ldg(bias + n0 + col4 + 2);
    bv[3] = __ldg(bias + n0 + col4 + 3);
    #pragma unroll
    for (int i = 0; i < 32; i++) {
        int row = (tid >> 5) + i * 4;
        const float* src = Cs + row * CSTR + col4;
        float4 v;
        v.x = src[0] + bv[0];
        v.y = src[1] + bv[1];
        v.z = src[2] + bv[2];
        v.w = src[3] + bv[3];
        *(float4*)(C + (size_t)(m0 + row) * D_MODEL + n0 + col4) = v;
    }
}

// ---------------------------------------------------------------------------
// Flash attention: per (q-tile 128, bh). 256 threads, 8 warps x (16 rows, 128 cols).
// Online softmax; K/V tiles pipelined across phases. (Unchanged — passing.)
// ---------------------------------------------------------------------------
#define FA_SROW 132
#define FA_TILE (128*FA_SROW)
#define FA_SMEM_SZ (3*FA_TILE*4)      // 202752 bytes

__global__ void __launch_bounds__(256, 1)
fa_kernel(const float* __restrict__ q, const float* __restrict__ k,
          const float* __restrict__ vt, float* __restrict__ att)
{
    extern __shared__ float sm[];
    float* sQP = sm;
    float* sK  = sm + FA_TILE;
    float* sV  = sm + 2 * FA_TILE;
    const uint32_t uQP = smem_u32(sQP);
    const uint32_t uK  = smem_u32(sK);
    const uint32_t uV  = smem_u32(sV);

    const int tid = threadIdx.x;
    const int wid = tid >> 5;
    const int lane = tid & 31;
    const int group = lane >> 2;
    const int qd = lane & 3;
    const int bh = blockIdx.y;
    const int b = bh >> 4, h = bh & 15;
    const int q0 = blockIdx.x * 128;

    const float* Qg = q + ((size_t)(b * S_LEN + q0)) * D_MODEL + h * HDIM;
    const float* Kg = k + ((size_t)b * S_LEN) * D_MODEL + h * HDIM;
    const float* Vg = vt + (size_t)bh * HDIM * S_LEN;

    #pragma unroll
    for (int i = 0; i < 16; i++) {
        int idx = i * 256 + tid;
        int r = idx >> 5, c = (idx & 31) * 4;
        cp16(uQP + (uint32_t)(r * FA_SROW + c) * 4, Qg + (size_t)r * D_MODEL + c);
    }
    cp_commit();
    #pragma unroll
    for (int i = 0; i < 16; i++) {
        int idx = i * 256 + tid;
        int r = idx >> 5, c = (idx & 31) * 4;
        cp16(uK + (uint32_t)(r * FA_SROW + c) * 4, Kg + (size_t)r * D_MODEL + c);
    }
    cp_commit();
    cp_wait<1>();
    __syncthreads();

    uint32_t qa[16][4];
    {
        const float* base = sQP + (wid * 16 + group) * FA_SROW;
        #pragma unroll
        for (int kk = 0; kk < 16; kk++) {
            qa[kk][0] = __float_as_uint(base[kk * 8 + qd]);
            qa[kk][1] = __float_as_uint(base[8 * FA_SROW + kk * 8 + qd]);
            qa[kk][2] = __float_as_uint(base[kk * 8 + qd + 4]);
            qa[kk][3] = __float_as_uint(base[8 * FA_SROW + kk * 8 + qd + 4]);
        }
    }
    __syncthreads();
    #pragma unroll
    for (int i = 0; i < 16; i++) {
        int idx = i * 256 + tid;
        int r = idx >> 5, c = (idx & 31) * 4;
        cp16(uV + (uint32_t)(r * FA_SROW + c) * 4, Vg + (size_t)r * S_LEN + c);
    }
    cp_commit();

    const float alpha = 0.08838834764831843f;
    float m0 = -1e30f, m1 = -1e30f, l0 = 0.0f, l1 = 0.0f;
    float oacc[16][4];
    #pragma unroll
    for (int nt = 0; nt < 16; nt++)
        #pragma unroll
        for (int i = 0; i < 4; i++) oacc[nt][i] = 0.0f;

    float* prow = sQP + (wid * 16 + group) * FA_SROW;

    for (int it = 0; it < 16; it++) {
        cp_wait<1>();
        __syncthreads();

        float sacc[16][4];
        #pragma unroll
        for (int nt = 0; nt < 16; nt++)
            #pragma unroll
            for (int i = 0; i < 4; i++) sacc[nt][i] = 0.0f;

        #pragma unroll
        for (int kk = 0; kk < 16; kk++) {
            const int colk = kk * 8 + qd;
            #pragma unroll
            for (int nt = 0; nt < 16; nt++) {
                uint32_t bf[2];
                const float* bp = sK + (nt * 8 + group) * FA_SROW + colk;
                bf[0] = __float_as_uint(bp[0]);
                bf[1] = __float_as_uint(bp[4]);
                mma_tf32(sacc[nt], qa[kk], bf);
            }
        }
        __syncthreads();
        if (it + 1 < 16) {
            const float* Kn = Kg + (size_t)(it + 1) * 128 * D_MODEL;
            #pragma unroll
            for (int i = 0; i < 16; i++) {
                int idx = i * 256 + tid;
                int r = idx >> 5, c = (idx & 31) * 4;
                cp16(uK + (uint32_t)(r * FA_SROW + c) * 4, Kn + (size_t)r * D_MODEL + c);
            }
            cp_commit();
        }

        float mxa = -1e30f, mxb = -1e30f;
        #pragma unroll
        for (int nt = 0; nt < 16; nt++) {
            sacc[nt][0] *= alpha; sacc[nt][1] *= alpha;
            sacc[nt][2] *= alpha; sacc[nt][3] *= alpha;
            mxa = fmaxf(mxa, fmaxf(sacc[nt][0], sacc[nt][1]));
            mxb = fmaxf(mxb, fmaxf(sacc[nt][2], sacc[nt][3]));
        }
        mxa = fmaxf(mxa, __shfl_xor_sync(0xFFFFFFFF, mxa, 1));
        mxa = fmaxf(mxa, __shfl_xor_sync(0xFFFFFFFF, mxa, 2));
        mxb = fmaxf(mxb, __shfl_xor_sync(0xFFFFFFFF, mxb, 1));
        mxb = fmaxf(mxb, __shfl_xor_sync(0xFFFFFFFF, mxb, 2));
        float na = fmaxf(m0, mxa), nb = fmaxf(m1, mxb);
        float fa_ = __expf(m0 - na), fb_ = __expf(m1 - nb);
        float psa = 0.0f, psb = 0.0f;
        #pragma unroll
        for (int nt = 0; nt < 16; nt++) {
            sacc[nt][0] = __expf(sacc[nt][0] - na);
            sacc[nt][1] = __expf(sacc[nt][1] - na);
            sacc[nt][2] = __expf(sacc[nt][2] - nb);
            sacc[nt][3] = __expf(sacc[nt][3] - nb);
            psa += sacc[nt][0] + sacc[nt][1];
            psb += sacc[nt][2] + sacc[nt][3];
        }
        psa += __shfl_xor_sync(0xFFFFFFFF, psa, 1);
        psa += __shfl_xor_sync(0xFFFFFFFF, psa, 2);
        psb += __shfl_xor_sync(0xFFFFFFFF, psb, 1);
        psb += __shfl_xor_sync(0xFFFFFFFF, psb, 2);
        l0 = l0 * fa_ + psa; l1 = l1 * fb_ + psb;
        m0 = na; m1 = nb;
        #pragma unroll
        for (int nt = 0; nt < 16; nt++) {
            oacc[nt][0] *= fa_; oacc[nt][1] *= fa_;
            oacc[nt][2] *= fb_; oacc[nt][3] *= fb_;
        }
        #pragma unroll
        for (int nt = 0; nt < 16; nt++) {
            int cb = nt * 8 + 2 * qd;
            *(float2*)(prow + cb) =
                make_float2(tf32r(sacc[nt][0]), tf32r(sacc[nt][1]));
            *(float2*)(prow + 8 * FA_SROW + cb) =
                make_float2(tf32r(sacc[nt][2]), tf32r(sacc[nt][3]));
        }

        if (it + 1 < 16) cp_wait<1>(); else cp_wait<0>();
        __syncthreads();

        #pragma unroll
        for (int kk = 0; kk < 16; kk++) {
            const int colk = kk * 8 + qd;
            uint32_t pa[4];
            pa[0] = __float_as_uint(prow[colk]);
            pa[1] = __float_as_uint(prow[8 * FA_SROW + colk]);
            pa[2] = __float_as_uint(prow[colk + 4]);
            pa[3] = __float_as_uint(prow[8 * FA_SROW + colk + 4]);
            #pragma unroll
            for (int nt = 0; nt < 16; nt++) {
                uint32_t bf[2];
                const float* bp = sV + (nt * 8 + group) * FA_SROW + colk;
                bf[0] = __float_as_uint(bp[0]);
                bf[1] = __float_as_uint(bp[4]);
                mma_tf32(oacc[nt], pa, bf);
            }
        }
        __syncthreads();
        if (it + 1 < 16) {
            const float* Vn = Vg + (it + 1) * 128;
            #pragma unroll
            for (int i = 0; i < 16; i++) {
                int idx = i * 256 + tid;
                int r = idx >> 5, c = (idx & 31) * 4;
                cp16(uV + (uint32_t)(r * FA_SROW + c) * 4, Vn + (size_t)r * S_LEN + c);
            }
            cp_commit();
        }
    }

    float inv0 = 1.0f / l0, inv1 = 1.0f / l1;
    int ra = q0 + wid * 16 + group;
    float* outa = att + (size_t)(b * S_LEN + ra) * D_MODEL + h * HDIM;
    float* outb = outa + 8 * (size_t)D_MODEL;
    #pragma unroll
    for (int nt = 0; nt < 16; nt++) {
        int cb = nt * 8 + 2 * qd;
        *(float2*)(outa + cb) =
            make_float2(tf32r(oacc[nt][0] * inv0), tf32r(oacc[nt][1] * inv0));
        *(float2*)(outb + cb) =
            make_float2(tf32r(oacc[nt][2] * inv1), tf32r(oacc[nt][3] * inv1));
    }
}

// ---------------------------------------------------------------------------
// Launch
// ---------------------------------------------------------------------------
extern "C" void kernel_launch(void* const* d_in, const int* in_sizes, int n_in,
                              void* d_out, int out_size) {
    const float* x  = (const float*)d_in[0];
    const float* Wq = (const float*)d_in[1];
    const float* bq = (const float*)d_in[2];
    const float* Wk = (const float*)d_in[3];
    const float* bk = (const float*)d_in[4];
    const float* Wv = (const float*)d_in[5];
    const float* bv = (const float*)d_in[6];
    const float* Wo = (const float*)d_in[7];
    const float* bo = (const float*)d_in[8];
    float* out = (float*)d_out;

    float *q, *k, *vt, *att, *wt;
    cudaGetSymbolAddress((void**)&q,   g_q);
    cudaGetSymbolAddress((void**)&k,   g_k);
    cudaGetSymbolAddress((void**)&vt,  g_vt);
    cudaGetSymbolAddress((void**)&att, g_att);
    cudaGetSymbolAddress((void**)&wt,  g_wt);
    float* wt0 = wt;
    float* wt1 = wt + (size_t)D_MODEL * D_MODEL;
    float* wt2 = wt + 2 * (size_t)D_MODEL * D_MODEL;
    float* wt3 = wt + 3 * (size_t)D_MODEL * D_MODEL;
    float* xr = att;   // att buffer reused as tf32-rounded x during projections

    cudaFuncSetAttribute((const void*)tc_gemm_qkv,
                         cudaFuncAttributeMaxDynamicSharedMemorySize, GEMM_SMEM_SZ);
    cudaFuncSetAttribute((const void*)tc_gemm_o,
                         cudaFuncAttributeMaxDynamicSharedMemorySize, GEMM_SMEM_SZ);
    cudaFuncSetAttribute((const void*)fa_kernel,
                         cudaFuncAttributeMaxDynamicSharedMemorySize, FA_SMEM_SZ);

    // 0. preprocessing: all W^T in one launch; x rounded; RoPE tables
    dim3 tb(32, 8);
    dim3 tg4(D_MODEL / 32, D_MODEL / 32, 4);
    transpose4_kernel<<<tg4, tb>>>(Wq, Wk, Wv, Wo, wt);
    int nx = NB * S_LEN * D_MODEL;
    round_copy_kernel<<<(nx + 255) / 256, 256>>>(x, xr, nx);
    rope_tables_kernel<<<(S_LEN * HALF_HD + 255) / 256, 256>>>();

    // 1. QKV projections in one launch (z=0:Q+RoPE, 1:K+RoPE, 2:V^T)
    dim3 gQKV(D_MODEL / 128, (NB * S_LEN) / 128, 3);    // (16, 32, 3)
    tc_gemm_qkv<<<gQKV, 128, GEMM_SMEM_SZ>>>(xr, wt0, wt1, wt2, bq, bk, bv,
                                             q, k, vt);

    // 2. fused attention (QK^T + softmax + PV), writes att (overwrites xr — safe)
    dim3 gFA(S_LEN / 128, BH);                          // (16, 32)
    fa_kernel<<<gFA, 256, FA_SMEM_SZ>>>(q, k, vt, att);

    // 3. out = att @ Wo + bo
    dim3 gO(D_MODEL / 128, (NB * S_LEN) / 128);         // (16, 32)
    tc_gemm_o<<<gO, 128, GEMM_SMEM_SZ>>>(att, wt3, bo, out);
}